// round 10
// baseline (speedup 1.0000x reference)
#include <cuda_runtime.h>
#include <cstdint>

#define HW_ (128*128)
#define NTOT (16*64)

__device__ float g_Q[NTOT * HW_];
__device__ float g_V[NTOT * HW_];
__device__ float g_K[NTOT * HW_];

// ---- bf16x3 helpers ---------------------------------------------------------
__device__ __forceinline__ void mma_bf16(float c[4], const uint32_t a[4],
                                         const uint32_t b0, const uint32_t b1) {
    asm volatile(
        "mma.sync.aligned.m16n8k16.row.col.f32.bf16.bf16.f32 "
        "{%0,%1,%2,%3}, {%4,%5,%6,%7}, {%8,%9}, {%0,%1,%2,%3};"
        : "+f"(c[0]), "+f"(c[1]), "+f"(c[2]), "+f"(c[3])
        : "r"(a[0]), "r"(a[1]), "r"(a[2]), "r"(a[3]), "r"(b0), "r"(b1));
}

// Split (x,y) into packed bf16x2 hi and lo parts. Low half = x (even k).
__device__ __forceinline__ void bf16x2_split(float x, float y,
                                             uint32_t& hi2, uint32_t& lo2) {
    uint32_t h;
    asm("cvt.rn.bf16x2.f32 %0, %1, %2;" : "=r"(h) : "f"(y), "f"(x));
    float xh = __uint_as_float(h << 16);
    float yh = __uint_as_float(h & 0xffff0000u);
    float xl = x - xh;
    float yl = y - yh;
    hi2 = h;
    asm("cvt.rn.bf16x2.f32 %0, %1, %2;" : "=r"(lo2) : "f"(yl), "f"(xl));
}

// ---------------------------------------------------------------------------
// Kernel 1: fused 1x1-conv projections, bf16x3 tensor cores.
// 512 thr / 16 warps. Warp (wb, wh): pixel sub-tile wb*16, channel half wh*32.
// Weights pre-split into packed bf16x2 pairs; X/E staged transposed.
// ---------------------------------------------------------------------------
#define LDXT 68   // Xt row stride (uints/floats): 64 ch + pad
#define LDET 20   // Et row stride: 16 ch + pad
#define LDW  36   // packed-pair stride for W2/W3 (32 pairs + pad)
#define LDW1 12   // packed-pair stride for W1 (8 pairs + pad)

__global__ __launch_bounds__(512) void qvk_kernel(
    const float* __restrict__ x, const float* __restrict__ e,
    const float* __restrict__ W1, const float* __restrict__ b1,
    const float* __restrict__ W2, const float* __restrict__ b2,
    const float* __restrict__ W3, const float* __restrict__ b3)
{
    extern __shared__ float sm[];
    uint32_t* W2h = (uint32_t*)sm;           // [64][LDW]
    uint32_t* W2l = W2h + 64*LDW;
    uint32_t* W3h = W2l + 64*LDW;
    uint32_t* W3l = W3h + 64*LDW;
    uint32_t* W1h = W3l + 64*LDW;            // [64][LDW1]
    uint32_t* W1l = W1h + 64*LDW1;
    float* b1s = (float*)(W1l + 64*LDW1);
    float* b2s = b1s + 64;
    float* b3s = b2s + 64;
    float* Xt  = b3s + 64;                   // [128][LDXT]  X transposed
    float* Et  = Xt + 128*LDXT;              // [128][LDET]  E transposed

    const int tid  = threadIdx.x;
    const int b    = blockIdx.y;
    const int pblk = blockIdx.x * 128;

    // Pre-split weights into packed bf16x2 pairs
    for (int idx = tid; idx < 2048; idx += 512) {
        int o = idx >> 5, p = idx & 31, c = 2*p;
        uint32_t h, l;
        bf16x2_split(W2[o*64 + c], W2[o*64 + c + 1], h, l);
        W2h[o*LDW + p] = h; W2l[o*LDW + p] = l;
        bf16x2_split(W3[o*64 + c], W3[o*64 + c + 1], h, l);
        W3h[o*LDW + p] = h; W3l[o*LDW + p] = l;
    }
    for (int idx = tid; idx < 512; idx += 512) {
        int o = idx >> 3, p = idx & 7, c = 2*p;
        uint32_t h, l;
        bf16x2_split(W1[o*16 + c], W1[o*16 + c + 1], h, l);
        W1h[o*LDW1 + p] = h; W1l[o*LDW1 + p] = l;
    }
    if (tid < 64) { b1s[tid] = b1[tid]; b2s[tid] = b2[tid]; b3s[tid] = b3[tid]; }

    // Stage X, E transposed (pixel-major)
    const float* xb = x + b*64*HW_ + pblk;
    const float* eb = e + b*16*HW_ + pblk;
    for (int idx = tid; idx < 64*128; idx += 512) {
        int c = idx >> 7, p = idx & 127;
        Xt[p*LDXT + c] = xb[c*HW_ + p];
    }
    for (int idx = tid; idx < 16*128; idx += 512) {
        int c = idx >> 7, p = idx & 127;
        Et[p*LDET + c] = eb[c*HW_ + p];
    }
    __syncthreads();

    const int warp = tid >> 5;
    const int lane = tid & 31;
    const int g4 = lane >> 2;
    const int tg = lane & 3;
    const int wb = warp & 7;
    const int wh = warp >> 3;
    const int p0 = wb*16;
    const int o0 = wh*32;

    float accV[2][2][4], accK[2][2][4], accQ[2][2][4];
    #pragma unroll
    for (int mt = 0; mt < 2; mt++) {
        int r = o0 + mt*16 + g4;
        float v0 = b2s[r], v1 = b2s[r+8];
        float k0 = b3s[r], k1 = b3s[r+8];
        float q0 = b1s[r], q1 = b1s[r+8];
        #pragma unroll
        for (int ntl = 0; ntl < 2; ntl++) {
            accV[mt][ntl][0] = v0; accV[mt][ntl][1] = v0;
            accV[mt][ntl][2] = v1; accV[mt][ntl][3] = v1;
            accK[mt][ntl][0] = k0; accK[mt][ntl][1] = k0;
            accK[mt][ntl][2] = k1; accK[mt][ntl][3] = k1;
            accQ[mt][ntl][0] = q0; accQ[mt][ntl][1] = q0;
            accQ[mt][ntl][2] = q1; accQ[mt][ntl][3] = q1;
        }
    }

    // ---- V, K over C=64: 4 k16 steps
    #pragma unroll
    for (int ks = 0; ks < 4; ks++) {
        const int kb = 16*ks + 2*tg;
        uint32_t bh[2][2], bl[2][2];
        #pragma unroll
        for (int ntl = 0; ntl < 2; ntl++) {
            int pcol = p0 + ntl*8 + g4;
            float2 x0 = *(const float2*)&Xt[pcol*LDXT + kb];
            float2 x1 = *(const float2*)&Xt[pcol*LDXT + kb + 8];
            bf16x2_split(x0.x, x0.y, bh[ntl][0], bl[ntl][0]);
            bf16x2_split(x1.x, x1.y, bh[ntl][1], bl[ntl][1]);
        }
        #pragma unroll
        for (int mt = 0; mt < 2; mt++) {
            const int rb = (o0 + mt*16 + g4)*LDW + 8*ks + tg;
            uint32_t ah[4], al[4];
            ah[0] = W2h[rb];           al[0] = W2l[rb];
            ah[1] = W2h[rb + 8*LDW];   al[1] = W2l[rb + 8*LDW];
            ah[2] = W2h[rb + 4];       al[2] = W2l[rb + 4];
            ah[3] = W2h[rb + 8*LDW+4]; al[3] = W2l[rb + 8*LDW+4];
            #pragma unroll
            for (int ntl = 0; ntl < 2; ntl++) {
                mma_bf16(accV[mt][ntl], ah, bh[ntl][0], bh[ntl][1]);
                mma_bf16(accV[mt][ntl], al, bh[ntl][0], bh[ntl][1]);
                mma_bf16(accV[mt][ntl], ah, bl[ntl][0], bl[ntl][1]);
            }
            ah[0] = W3h[rb];           al[0] = W3l[rb];
            ah[1] = W3h[rb + 8*LDW];   al[1] = W3l[rb + 8*LDW];
            ah[2] = W3h[rb + 4];       al[2] = W3l[rb + 4];
            ah[3] = W3h[rb + 8*LDW+4]; al[3] = W3l[rb + 8*LDW+4];
            #pragma unroll
            for (int ntl = 0; ntl < 2; ntl++) {
                mma_bf16(accK[mt][ntl], ah, bh[ntl][0], bh[ntl][1]);
                mma_bf16(accK[mt][ntl], al, bh[ntl][0], bh[ntl][1]);
                mma_bf16(accK[mt][ntl], ah, bl[ntl][0], bl[ntl][1]);
            }
        }
    }

    // ---- Q over C1=16: 1 k16 step
    {
        const int kb = 2*tg;
        uint32_t bh[2][2], bl[2][2];
        #pragma unroll
        for (int ntl = 0; ntl < 2; ntl++) {
            int pcol = p0 + ntl*8 + g4;
            float2 e0 = *(const float2*)&Et[pcol*LDET + kb];
            float2 e1 = *(const float2*)&Et[pcol*LDET + kb + 8];
            bf16x2_split(e0.x, e0.y, bh[ntl][0], bl[ntl][0]);
            bf16x2_split(e1.x, e1.y, bh[ntl][1], bl[ntl][1]);
        }
        #pragma unroll
        for (int mt = 0; mt < 2; mt++) {
            const int rb = (o0 + mt*16 + g4)*LDW1 + tg;
            uint32_t ah[4], al[4];
            ah[0] = W1h[rb];            al[0] = W1l[rb];
            ah[1] = W1h[rb + 8*LDW1];   al[1] = W1l[rb + 8*LDW1];
            ah[2] = W1h[rb + 4];        al[2] = W1l[rb + 4];
            ah[3] = W1h[rb + 8*LDW1+4]; al[3] = W1l[rb + 8*LDW1+4];
            #pragma unroll
            for (int ntl = 0; ntl < 2; ntl++) {
                mma_bf16(accQ[mt][ntl], ah, bh[ntl][0], bh[ntl][1]);
                mma_bf16(accQ[mt][ntl], al, bh[ntl][0], bh[ntl][1]);
                mma_bf16(accQ[mt][ntl], ah, bl[ntl][0], bl[ntl][1]);
            }
        }
    }

    // ---- Store
    #pragma unroll
    for (int mt = 0; mt < 2; mt++) {
        int r = o0 + mt*16 + g4;
        #pragma unroll
        for (int ntl = 0; ntl < 2; ntl++) {
            int pc = pblk + p0 + ntl*8 + 2*tg;
            int i0 = (b*64 + r)*HW_ + pc;
            int i1 = (b*64 + r + 8)*HW_ + pc;
            *(float2*)&g_V[i0] = make_float2(accV[mt][ntl][0], accV[mt][ntl][1]);
            *(float2*)&g_V[i1] = make_float2(accV[mt][ntl][2], accV[mt][ntl][3]);
            *(float2*)&g_K[i0] = make_float2(accK[mt][ntl][0], accK[mt][ntl][1]);
            *(float2*)&g_K[i1] = make_float2(accK[mt][ntl][2], accK[mt][ntl][3]);
            *(float2*)&g_Q[i0] = make_float2(accQ[mt][ntl][0], accQ[mt][ntl][1]);
            *(float2*)&g_Q[i1] = make_float2(accQ[mt][ntl][2], accQ[mt][ntl][3]);
        }
    }
}

// ---------------------------------------------------------------------------
// Kernel 2: per-head attention, bf16x3 tensor cores, 1024 threads (32 warps).
// Phase C uses K transposed in smem (contiguous float2 b-fragments).
// ---------------------------------------------------------------------------
#define LDA 132

__global__ __launch_bounds__(1024) void attn_kernel(float* __restrict__ out)
{
    extern __shared__ float sm[];
    float* A    = sm;              // Q[h][w] -> later P[h][g]
    float* Bm   = sm + 128*LDA;    // V[g][w] -> later Kt[w][g]
    float* redM = sm + 2*128*LDA;  // [4][128]
    float* redS = redM + 4*128;    // [4][128]

    const int tid  = threadIdx.x;
    const int warp = tid >> 5;
    const int lane = tid & 31;
    const int wb   = warp & 7;
    const int wq   = warp >> 3;
    const int n    = blockIdx.x;
    const float* Q = g_Q + n*HW_;
    const float* V = g_V + n*HW_;
    const float* K = g_K + n*HW_;

    for (int idx = tid; idx < 128*32; idx += 1024) {
        int row = idx >> 5, c4 = (idx & 31) * 4;
        *(float4*)&A[row*LDA + c4]  = *(const float4*)&Q[row*128 + c4];
        *(float4*)&Bm[row*LDA + c4] = *(const float4*)&V[row*128 + c4];
    }
    __syncthreads();

    const int g4 = lane >> 2;
    const int tg = lane & 3;
    const int r0 = wb*16 + g4;
    const int nt0 = wq*4;

    float acc[4][4];
    #pragma unroll
    for (int j = 0; j < 4; j++)
        #pragma unroll
        for (int i = 0; i < 4; i++) acc[j][i] = 0.0f;

    // ---- Phase A: S = Q @ V^T (8 k16 steps)
    #pragma unroll 1
    for (int k = 0; k < 8; k++) {
        const int kb = k*16 + 2*tg;
        float2 a0 = *(const float2*)&A[r0*LDA + kb];
        float2 a1 = *(const float2*)&A[(r0+8)*LDA + kb];
        float2 a2 = *(const float2*)&A[r0*LDA + kb + 8];
        float2 a3 = *(const float2*)&A[(r0+8)*LDA + kb + 8];
        uint32_t ah[4], al[4];
        bf16x2_split(a0.x, a0.y, ah[0], al[0]);
        bf16x2_split(a1.x, a1.y, ah[1], al[1]);
        bf16x2_split(a2.x, a2.y, ah[2], al[2]);
        bf16x2_split(a3.x, a3.y, ah[3], al[3]);
        #pragma unroll
        for (int j = 0; j < 4; j++) {
            const int gc = (nt0 + j)*8 + g4;
            float2 v0 = *(const float2*)&Bm[gc*LDA + kb];
            float2 v1 = *(const float2*)&Bm[gc*LDA + kb + 8];
            uint32_t bh0, bl0, bh1, bl1;
            bf16x2_split(v0.x, v0.y, bh0, bl0);
            bf16x2_split(v1.x, v1.y, bh1, bl1);
            mma_bf16(acc[j], ah, bh0, bh1);
            mma_bf16(acc[j], al, bh0, bh1);
            mma_bf16(acc[j], ah, bl0, bl1);
        }
    }

    // ---- Softmax (4-warp row groups)
    float m1 = -1e30f, m2 = -1e30f;
    #pragma unroll
    for (int j = 0; j < 4; j++) {
        m1 = fmaxf(m1, fmaxf(acc[j][0], acc[j][1]));
        m2 = fmaxf(m2, fmaxf(acc[j][2], acc[j][3]));
    }
    #pragma unroll
    for (int off = 1; off < 4; off <<= 1) {
        m1 = fmaxf(m1, __shfl_xor_sync(0xFFFFFFFFu, m1, off));
        m2 = fmaxf(m2, __shfl_xor_sync(0xFFFFFFFFu, m2, off));
    }
    if (tg == 0) {
        redM[wq*128 + r0]     = m1;
        redM[wq*128 + r0 + 8] = m2;
    }
    __syncthreads();

    const float gm1 = fmaxf(fmaxf(redM[r0],       redM[128 + r0]),
                            fmaxf(redM[256 + r0], redM[384 + r0]));
    const float gm2 = fmaxf(fmaxf(redM[r0+8],       redM[128 + r0+8]),
                            fmaxf(redM[256 + r0+8], redM[384 + r0+8]));

    float s1 = 0.0f, s2 = 0.0f;
    #pragma unroll
    for (int j = 0; j < 4; j++) {
        acc[j][0] = __expf(acc[j][0] - gm1);
        acc[j][1] = __expf(acc[j][1] - gm1);
        acc[j][2] = __expf(acc[j][2] - gm2);
        acc[j][3] = __expf(acc[j][3] - gm2);
        s1 += acc[j][0] + acc[j][1];
        s2 += acc[j][2] + acc[j][3];
    }
    #pragma unroll
    for (int off = 1; off < 4; off <<= 1) {
        s1 += __shfl_xor_sync(0xFFFFFFFFu, s1, off);
        s2 += __shfl_xor_sync(0xFFFFFFFFu, s2, off);
    }
    if (tg == 0) {
        redS[wq*128 + r0]     = s1;
        redS[wq*128 + r0 + 8] = s2;
    }

    // Store unnormalized P into A; stage K TRANSPOSED into Bm
    #pragma unroll
    for (int j = 0; j < 4; j++) {
        const int cb = (nt0 + j)*8 + 2*tg;
        *(float2*)&A[r0*LDA     + cb] = make_float2(acc[j][0], acc[j][1]);
        *(float2*)&A[(r0+8)*LDA + cb] = make_float2(acc[j][2], acc[j][3]);
    }
    for (int idx = tid; idx < HW_; idx += 1024) {
        int g = idx >> 7, w = idx & 127;
        Bm[w*LDA + g] = K[idx];          // Kt[w][g]
    }
    __syncthreads();

    const float inv1 = 1.0f / (redS[r0] + redS[128 + r0] +
                               redS[256 + r0] + redS[384 + r0]);
    const float inv2 = 1.0f / (redS[r0+8] + redS[128 + r0+8] +
                               redS[256 + r0+8] + redS[384 + r0+8]);

    // ---- Phase C: ctx = P @ K (8 k16 steps; B from Kt)
    float oac[4][4];
    #pragma unroll
    for (int j = 0; j < 4; j++)
        #pragma unroll
        for (int i = 0; i < 4; i++) oac[j][i] = 0.0f;

    #pragma unroll 1
    for (int k = 0; k < 8; k++) {
        const int kb = k*16 + 2*tg;
        float2 a0 = *(const float2*)&A[r0*LDA + kb];
        float2 a1 = *(const float2*)&A[(r0+8)*LDA + kb];
        float2 a2 = *(const float2*)&A[r0*LDA + kb + 8];
        float2 a3 = *(const float2*)&A[(r0+8)*LDA + kb + 8];
        uint32_t ah[4], al[4];
        bf16x2_split(a0.x, a0.y, ah[0], al[0]);
        bf16x2_split(a1.x, a1.y, ah[1], al[1]);
        bf16x2_split(a2.x, a2.y, ah[2], al[2]);
        bf16x2_split(a3.x, a3.y, ah[3], al[3]);
        #pragma unroll
        for (int j = 0; j < 4; j++) {
            const int nc = (nt0 + j)*8 + g4;
            float2 k0 = *(const float2*)&Bm[nc*LDA + kb];
            float2 k1 = *(const float2*)&Bm[nc*LDA + kb + 8];
            uint32_t bh0, bl0, bh1, bl1;
            bf16x2_split(k0.x, k0.y, bh0, bl0);
            bf16x2_split(k1.x, k1.y, bh1, bl1);
            mma_bf16(oac[j], ah, bh0, bh1);
            mma_bf16(oac[j], al, bh0, bh1);
            mma_bf16(oac[j], ah, bl0, bl1);
        }
    }

    // Epilogue
    #pragma unroll
    for (int j = 0; j < 4; j++) {
        const int cb = (nt0 + j)*8 + 2*tg;
        *(float2*)&out[n*HW_ + r0*128 + cb] =
            make_float2(oac[j][0]*inv1, oac[j][1]*inv1);
        *(float2*)&out[n*HW_ + (r0+8)*128 + cb] =
            make_float2(oac[j][2]*inv2, oac[j][3]*inv2);
    }
}

// ---------------------------------------------------------------------------
extern "C" void kernel_launch(void* const* d_in, const int* in_sizes, int n_in,
                              void* d_out, int out_size)
{
    const float* x  = (const float*)d_in[0];
    const float* e  = (const float*)d_in[1];
    const float* W1 = (const float*)d_in[2];
    const float* b1 = (const float*)d_in[3];
    const float* W2 = (const float*)d_in[4];
    const float* b2 = (const float*)d_in[5];
    const float* W3 = (const float*)d_in[6];
    const float* b3 = (const float*)d_in[7];
    float* out = (float*)d_out;

    const int smem1 = (4*64*LDW + 2*64*LDW1 + 3*64 + 128*LDXT + 128*LDET)
                      * (int)sizeof(float);
    cudaFuncSetAttribute(qvk_kernel, cudaFuncAttributeMaxDynamicSharedMemorySize, smem1);
    qvk_kernel<<<dim3(128, 16), 512, smem1>>>(x, e, W1, b1, W2, b2, W3, b3);

    const int smem2 = (2*128*LDA + 8*128) * (int)sizeof(float);
    cudaFuncSetAttribute(attn_kernel, cudaFuncAttributeMaxDynamicSharedMemorySize, smem2);
    attn_kernel<<<NTOT, 1024, smem2>>>(out);
}

// round 11
// speedup vs baseline: 1.4941x; 1.4941x over previous
#include <cuda_runtime.h>
#include <cstdint>

#define HW_ (128*128)
#define NTOT (16*64)
#define HWP (HW_/2)

__device__ uint32_t g_Qh[NTOT * HWP];
__device__ uint32_t g_Ql[NTOT * HWP];
__device__ uint32_t g_Vh[NTOT * HWP];
__device__ uint32_t g_Vl[NTOT * HWP];
__device__ float    g_K [NTOT * HW_];

// ---- bf16x3 helpers ---------------------------------------------------------
__device__ __forceinline__ void mma_bf16(float c[4], const uint32_t a[4],
                                         const uint32_t b0, const uint32_t b1) {
    asm volatile(
        "mma.sync.aligned.m16n8k16.row.col.f32.bf16.bf16.f32 "
        "{%0,%1,%2,%3}, {%4,%5,%6,%7}, {%8,%9}, {%0,%1,%2,%3};"
        : "+f"(c[0]), "+f"(c[1]), "+f"(c[2]), "+f"(c[3])
        : "r"(a[0]), "r"(a[1]), "r"(a[2]), "r"(a[3]), "r"(b0), "r"(b1));
}

// Split (x,y) into packed bf16x2 hi and lo. Low 16 bits = x (even k element).
__device__ __forceinline__ void bf16x2_split(float x, float y,
                                             uint32_t& hi2, uint32_t& lo2) {
    uint32_t h;
    asm("cvt.rn.bf16x2.f32 %0, %1, %2;" : "=r"(h) : "f"(y), "f"(x));
    float xh = __uint_as_float(h << 16);
    float yh = __uint_as_float(h & 0xffff0000u);
    float xl = x - xh;
    float yl = y - yh;
    hi2 = h;
    asm("cvt.rn.bf16x2.f32 %0, %1, %2;" : "=r"(lo2) : "f"(yl), "f"(xl));
}

// ---------------------------------------------------------------------------
// Kernel 1: fused 1x1-conv projections, bf16x3, pre-split operands in smem.
// 512 thr / 16 warps; ~86KB smem (2 CTAs/SM). Warp (wb pixel sub-tile,
// wh channel half). Q/V stored packed; K stored fp32.
// ---------------------------------------------------------------------------
#define LDW  36   // W2/W3 pair stride (32 pairs + pad)
#define LDW1 12   // W1 pair stride (8 pairs + pad)
#define LDXP 132  // Xp/Ep row stride (pixel dim + pad)

__global__ __launch_bounds__(512) void qvk_kernel(
    const float* __restrict__ x, const float* __restrict__ e,
    const float* __restrict__ W1, const float* __restrict__ b1,
    const float* __restrict__ W2, const float* __restrict__ b2,
    const float* __restrict__ W3, const float* __restrict__ b3)
{
    extern __shared__ uint32_t smu[];
    uint32_t* W2h = smu;                 // [64][LDW]
    uint32_t* W2l = W2h + 64*LDW;
    uint32_t* W3h = W2l + 64*LDW;
    uint32_t* W3l = W3h + 64*LDW;
    uint32_t* W1h = W3l + 64*LDW;        // [64][LDW1]
    uint32_t* W1l = W1h + 64*LDW1;
    uint32_t* Xh  = W1l + 64*LDW1;       // [32][LDXP] vertical pairs
    uint32_t* Xl  = Xh + 32*LDXP;
    uint32_t* Eh  = Xl + 32*LDXP;        // [8][LDXP]
    uint32_t* El  = Eh + 8*LDXP;
    float* b1s = (float*)(El + 8*LDXP);
    float* b2s = b1s + 64;
    float* b3s = b2s + 64;

    const int tid  = threadIdx.x;
    const int b    = blockIdx.y;
    const int pblk = blockIdx.x * 128;

    // Pre-split weights (horizontal pairs along c)
    for (int idx = tid; idx < 2048; idx += 512) {
        int o = idx >> 5, p = idx & 31, c = 2*p;
        uint32_t h, l;
        bf16x2_split(W2[o*64 + c], W2[o*64 + c + 1], h, l);
        W2h[o*LDW + p] = h; W2l[o*LDW + p] = l;
        bf16x2_split(W3[o*64 + c], W3[o*64 + c + 1], h, l);
        W3h[o*LDW + p] = h; W3l[o*LDW + p] = l;
    }
    if (tid < 512) {
        int o = tid >> 3, p = tid & 7, c = 2*p;
        uint32_t h, l;
        bf16x2_split(W1[o*16 + c], W1[o*16 + c + 1], h, l);
        W1h[o*LDW1 + p] = h; W1l[o*LDW1 + p] = l;
    }
    if (tid < 64) { b1s[tid] = b1[tid]; b2s[tid] = b2[tid]; b3s[tid] = b3[tid]; }

    // Stage X, E with VERTICAL channel pairs: Xp[cp][p] = pack(x[2cp][p], x[2cp+1][p])
    const float* xb = x + b*64*HW_ + pblk;
    const float* eb = e + b*16*HW_ + pblk;
    for (int idx = tid; idx < 32*128; idx += 512) {
        int cp = idx >> 7, p = idx & 127;
        uint32_t h, l;
        bf16x2_split(xb[(2*cp)*HW_ + p], xb[(2*cp+1)*HW_ + p], h, l);
        Xh[cp*LDXP + p] = h; Xl[cp*LDXP + p] = l;
    }
    for (int idx = tid; idx < 8*128; idx += 512) {
        int cp = idx >> 7, p = idx & 127;
        uint32_t h, l;
        bf16x2_split(eb[(2*cp)*HW_ + p], eb[(2*cp+1)*HW_ + p], h, l);
        Eh[cp*LDXP + p] = h; El[cp*LDXP + p] = l;
    }
    __syncthreads();

    const int warp = tid >> 5;
    const int lane = tid & 31;
    const int g4 = lane >> 2;
    const int tg = lane & 3;
    const int wb = warp & 7;
    const int wh = warp >> 3;
    const int p0 = wb*16;
    const int o0 = wh*32;

    float accV[2][2][4], accK[2][2][4], accQ[2][2][4];
    #pragma unroll
    for (int mt = 0; mt < 2; mt++) {
        int r = o0 + mt*16 + g4;
        float v0 = b2s[r], v1 = b2s[r+8];
        float k0 = b3s[r], k1 = b3s[r+8];
        float q0 = b1s[r], q1 = b1s[r+8];
        #pragma unroll
        for (int ntl = 0; ntl < 2; ntl++) {
            accV[mt][ntl][0] = v0; accV[mt][ntl][1] = v0;
            accV[mt][ntl][2] = v1; accV[mt][ntl][3] = v1;
            accK[mt][ntl][0] = k0; accK[mt][ntl][1] = k0;
            accK[mt][ntl][2] = k1; accK[mt][ntl][3] = k1;
            accQ[mt][ntl][0] = q0; accQ[mt][ntl][1] = q0;
            accQ[mt][ntl][2] = q1; accQ[mt][ntl][3] = q1;
        }
    }

    // ---- V, K over C=64: 4 k16 steps, zero in-loop ALU
    #pragma unroll
    for (int ks = 0; ks < 4; ks++) {
        uint32_t bh[2][2], bl[2][2];
        #pragma unroll
        for (int ntl = 0; ntl < 2; ntl++) {
            int pcol = p0 + ntl*8 + g4;
            bh[ntl][0] = Xh[(8*ks + tg)*LDXP + pcol];
            bl[ntl][0] = Xl[(8*ks + tg)*LDXP + pcol];
            bh[ntl][1] = Xh[(8*ks + tg + 4)*LDXP + pcol];
            bl[ntl][1] = Xl[(8*ks + tg + 4)*LDXP + pcol];
        }
        #pragma unroll
        for (int mt = 0; mt < 2; mt++) {
            const int rb = (o0 + mt*16 + g4)*LDW + 8*ks + tg;
            uint32_t ah[4], al[4];
            ah[0] = W2h[rb];           al[0] = W2l[rb];
            ah[1] = W2h[rb + 8*LDW];   al[1] = W2l[rb + 8*LDW];
            ah[2] = W2h[rb + 4];       al[2] = W2l[rb + 4];
            ah[3] = W2h[rb + 8*LDW+4]; al[3] = W2l[rb + 8*LDW+4];
            #pragma unroll
            for (int ntl = 0; ntl < 2; ntl++) {
                mma_bf16(accV[mt][ntl], ah, bh[ntl][0], bh[ntl][1]);
                mma_bf16(accV[mt][ntl], al, bh[ntl][0], bh[ntl][1]);
                mma_bf16(accV[mt][ntl], ah, bl[ntl][0], bl[ntl][1]);
            }
            ah[0] = W3h[rb];           al[0] = W3l[rb];
            ah[1] = W3h[rb + 8*LDW];   al[1] = W3l[rb + 8*LDW];
            ah[2] = W3h[rb + 4];       al[2] = W3l[rb + 4];
            ah[3] = W3h[rb + 8*LDW+4]; al[3] = W3l[rb + 8*LDW+4];
            #pragma unroll
            for (int ntl = 0; ntl < 2; ntl++) {
                mma_bf16(accK[mt][ntl], ah, bh[ntl][0], bh[ntl][1]);
                mma_bf16(accK[mt][ntl], al, bh[ntl][0], bh[ntl][1]);
                mma_bf16(accK[mt][ntl], ah, bl[ntl][0], bl[ntl][1]);
            }
        }
    }

    // ---- Q over C1=16: 1 k16 step
    {
        uint32_t bh[2][2], bl[2][2];
        #pragma unroll
        for (int ntl = 0; ntl < 2; ntl++) {
            int pcol = p0 + ntl*8 + g4;
            bh[ntl][0] = Eh[tg*LDXP + pcol];
            bl[ntl][0] = El[tg*LDXP + pcol];
            bh[ntl][1] = Eh[(tg+4)*LDXP + pcol];
            bl[ntl][1] = El[(tg+4)*LDXP + pcol];
        }
        #pragma unroll
        for (int mt = 0; mt < 2; mt++) {
            const int rb = (o0 + mt*16 + g4)*LDW1 + tg;
            uint32_t ah[4], al[4];
            ah[0] = W1h[rb];            al[0] = W1l[rb];
            ah[1] = W1h[rb + 8*LDW1];   al[1] = W1l[rb + 8*LDW1];
            ah[2] = W1h[rb + 4];        al[2] = W1l[rb + 4];
            ah[3] = W1h[rb + 8*LDW1+4]; al[3] = W1l[rb + 8*LDW1+4];
            #pragma unroll
            for (int ntl = 0; ntl < 2; ntl++) {
                mma_bf16(accQ[mt][ntl], ah, bh[ntl][0], bh[ntl][1]);
                mma_bf16(accQ[mt][ntl], al, bh[ntl][0], bh[ntl][1]);
                mma_bf16(accQ[mt][ntl], ah, bl[ntl][0], bl[ntl][1]);
            }
        }
    }

    // ---- Store: Q,V packed (adjacent-pixel pairs = attn phase-A k-pairs); K fp32
    #pragma unroll
    for (int mt = 0; mt < 2; mt++) {
        int r = o0 + mt*16 + g4;
        #pragma unroll
        for (int ntl = 0; ntl < 2; ntl++) {
            int pc = pblk + p0 + ntl*8 + 2*tg;
            int pq = pc >> 1;
            int n0 = b*64 + r, n1 = n0 + 8;
            uint32_t h, l;
            bf16x2_split(accQ[mt][ntl][0], accQ[mt][ntl][1], h, l);
            g_Qh[n0*HWP + pq] = h; g_Ql[n0*HWP + pq] = l;
            bf16x2_split(accQ[mt][ntl][2], accQ[mt][ntl][3], h, l);
            g_Qh[n1*HWP + pq] = h; g_Ql[n1*HWP + pq] = l;
            bf16x2_split(accV[mt][ntl][0], accV[mt][ntl][1], h, l);
            g_Vh[n0*HWP + pq] = h; g_Vl[n0*HWP + pq] = l;
            bf16x2_split(accV[mt][ntl][2], accV[mt][ntl][3], h, l);
            g_Vh[n1*HWP + pq] = h; g_Vl[n1*HWP + pq] = l;
            *(float2*)&g_K[n0*HW_ + pc] = make_float2(accK[mt][ntl][0], accK[mt][ntl][1]);
            *(float2*)&g_K[n1*HW_ + pc] = make_float2(accK[mt][ntl][2], accK[mt][ntl][3]);
        }
    }
}

// ---------------------------------------------------------------------------
// Kernel 2: per-head attention, bf16x3, pre-split operands, 1024 threads.
// A-buf: Qp -> Pp (horizontal pairs, [128][66]). B-buf: Vp [128][66] ->
// Kp [64][132] (vertical pairs for phase-C k over g-rows).
// ---------------------------------------------------------------------------
#define LDP 66
#define LDKP 132

__global__ __launch_bounds__(1024) void attn_kernel(float* __restrict__ out)
{
    extern __shared__ uint32_t smu[];
    uint32_t* Ah = smu;                  // [128][LDP]
    uint32_t* Al = Ah + 128*LDP;
    uint32_t* Bh = Al + 128*LDP;         // [128][LDP] as Vp / [64][LDKP] as Kp
    uint32_t* Bl = Bh + 128*LDP;
    float* redM = (float*)(Bl + 128*LDP);  // [4][128]
    float* redS = redM + 512;              // [4][128]

    const int tid  = threadIdx.x;
    const int warp = tid >> 5;
    const int lane = tid & 31;
    const int wb   = warp & 7;
    const int wq   = warp >> 3;
    const int n    = blockIdx.x;
    const uint32_t* Qh = g_Qh + n*HWP;
    const uint32_t* Ql = g_Ql + n*HWP;
    const uint32_t* Vh = g_Vh + n*HWP;
    const uint32_t* Vl = g_Vl + n*HWP;
    const float*    K  = g_K  + n*HW_;

    // Stage Qp, Vp (pure u32 copies — no conversion)
    for (int idx = tid; idx < HWP; idx += 1024) {
        int r = idx >> 6, c = idx & 63;
        Ah[r*LDP + c] = Qh[idx];
        Al[r*LDP + c] = Ql[idx];
        Bh[r*LDP + c] = Vh[idx];
        Bl[r*LDP + c] = Vl[idx];
    }
    __syncthreads();

    const int g4 = lane >> 2;
    const int tg = lane & 3;
    const int r0 = wb*16 + g4;
    const int nt0 = wq*4;

    float acc[4][4];
    #pragma unroll
    for (int j = 0; j < 4; j++)
        #pragma unroll
        for (int i = 0; i < 4; i++) acc[j][i] = 0.0f;

    // ---- Phase A: S = Q @ V^T (8 k16 steps, zero in-loop ALU)
    #pragma unroll 2
    for (int k = 0; k < 8; k++) {
        const int kp = k*8 + tg;
        uint32_t ah[4], al[4];
        ah[0] = Ah[r0*LDP + kp];         al[0] = Al[r0*LDP + kp];
        ah[1] = Ah[(r0+8)*LDP + kp];     al[1] = Al[(r0+8)*LDP + kp];
        ah[2] = Ah[r0*LDP + kp + 4];     al[2] = Al[r0*LDP + kp + 4];
        ah[3] = Ah[(r0+8)*LDP + kp + 4]; al[3] = Al[(r0+8)*LDP + kp + 4];
        #pragma unroll
        for (int j = 0; j < 4; j++) {
            const int gc = (nt0 + j)*8 + g4;
            uint32_t bh0 = Bh[gc*LDP + kp],     bl0 = Bl[gc*LDP + kp];
            uint32_t bh1 = Bh[gc*LDP + kp + 4], bl1 = Bl[gc*LDP + kp + 4];
            mma_bf16(acc[j], ah, bh0, bh1);
            mma_bf16(acc[j], al, bh0, bh1);
            mma_bf16(acc[j], ah, bl0, bl1);
        }
    }

    // ---- Softmax (4-warp row groups)
    float m1 = -1e30f, m2 = -1e30f;
    #pragma unroll
    for (int j = 0; j < 4; j++) {
        m1 = fmaxf(m1, fmaxf(acc[j][0], acc[j][1]));
        m2 = fmaxf(m2, fmaxf(acc[j][2], acc[j][3]));
    }
    #pragma unroll
    for (int off = 1; off < 4; off <<= 1) {
        m1 = fmaxf(m1, __shfl_xor_sync(0xFFFFFFFFu, m1, off));
        m2 = fmaxf(m2, __shfl_xor_sync(0xFFFFFFFFu, m2, off));
    }
    if (tg == 0) {
        redM[wq*128 + r0]     = m1;
        redM[wq*128 + r0 + 8] = m2;
    }
    __syncthreads();   // phase-A reads done + partial maxes visible

    const float gm1 = fmaxf(fmaxf(redM[r0],       redM[128 + r0]),
                            fmaxf(redM[256 + r0], redM[384 + r0]));
    const float gm2 = fmaxf(fmaxf(redM[r0+8],       redM[128 + r0+8]),
                            fmaxf(redM[256 + r0+8], redM[384 + r0+8]));

    float s1 = 0.0f, s2 = 0.0f;
    #pragma unroll
    for (int j = 0; j < 4; j++) {
        acc[j][0] = __expf(acc[j][0] - gm1);
        acc[j][1] = __expf(acc[j][1] - gm1);
        acc[j][2] = __expf(acc[j][2] - gm2);
        acc[j][3] = __expf(acc[j][3] - gm2);
        s1 += acc[j][0] + acc[j][1];
        s2 += acc[j][2] + acc[j][3];
    }
    #pragma unroll
    for (int off = 1; off < 4; off <<= 1) {
        s1 += __shfl_xor_sync(0xFFFFFFFFu, s1, off);
        s2 += __shfl_xor_sync(0xFFFFFFFFu, s2, off);
    }
    if (tg == 0) {
        redS[wq*128 + r0]     = s1;
        redS[wq*128 + r0 + 8] = s2;
    }

    // Store P split into A-buf (each thread's acc pair = one k-pair)
    #pragma unroll
    for (int j = 0; j < 4; j++) {
        const int pb = (nt0 + j)*4 + tg;
        uint32_t h, l;
        bf16x2_split(acc[j][0], acc[j][1], h, l);
        Ah[r0*LDP + pb] = h; Al[r0*LDP + pb] = l;
        bf16x2_split(acc[j][2], acc[j][3], h, l);
        Ah[(r0+8)*LDP + pb] = h; Al[(r0+8)*LDP + pb] = l;
    }
    // Stage K with VERTICAL pairs: Kp[gp][w] = pack(K[2gp][w], K[2gp+1][w])
    for (int idx = tid; idx < 64*128; idx += 1024) {
        int gp = idx >> 7, w = idx & 127;
        uint32_t h, l;
        bf16x2_split(K[(2*gp)*128 + w], K[(2*gp+1)*128 + w], h, l);
        Bh[gp*LDKP + w] = h; Bl[gp*LDKP + w] = l;
    }
    __syncthreads();   // P + Kp complete, partial sums visible

    const float inv1 = 1.0f / (redS[r0] + redS[128 + r0] +
                               redS[256 + r0] + redS[384 + r0]);
    const float inv2 = 1.0f / (redS[r0+8] + redS[128 + r0+8] +
                               redS[256 + r0+8] + redS[384 + r0+8]);

    // ---- Phase C: ctx = P @ K (8 k16 steps over g)
    float oac[4][4];
    #pragma unroll
    for (int j = 0; j < 4; j++)
        #pragma unroll
        for (int i = 0; i < 4; i++) oac[j][i] = 0.0f;

    #pragma unroll 2
    for (int k = 0; k < 8; k++) {
        const int kp = k*8 + tg;
        uint32_t ah[4], al[4];
        ah[0] = Ah[r0*LDP + kp];         al[0] = Al[r0*LDP + kp];
        ah[1] = Ah[(r0+8)*LDP + kp];     al[1] = Al[(r0+8)*LDP + kp];
        ah[2] = Ah[r0*LDP + kp + 4];     al[2] = Al[r0*LDP + kp + 4];
        ah[3] = Ah[(r0+8)*LDP + kp + 4]; al[3] = Al[(r0+8)*LDP + kp + 4];
        #pragma unroll
        for (int j = 0; j < 4; j++) {
            const int nc = (nt0 + j)*8 + g4;
            uint32_t bh0 = Bh[kp*LDKP + nc],       bl0 = Bl[kp*LDKP + nc];
            uint32_t bh1 = Bh[(kp+4)*LDKP + nc],   bl1 = Bl[(kp+4)*LDKP + nc];
            mma_bf16(oac[j], ah, bh0, bh1);
            mma_bf16(oac[j], al, bh0, bh1);
            mma_bf16(oac[j], ah, bl0, bl1);
        }
    }

    // Epilogue
    #pragma unroll
    for (int j = 0; j < 4; j++) {
        const int cb = (nt0 + j)*8 + 2*tg;
        *(float2*)&out[n*HW_ + r0*128 + cb] =
            make_float2(oac[j][0]*inv1, oac[j][1]*inv1);
        *(float2*)&out[n*HW_ + (r0+8)*128 + cb] =
            make_float2(oac[j][2]*inv2, oac[j][3]*inv2);
    }
}

// ---------------------------------------------------------------------------
extern "C" void kernel_launch(void* const* d_in, const int* in_sizes, int n_in,
                              void* d_out, int out_size)
{
    const float* x  = (const float*)d_in[0];
    const float* e  = (const float*)d_in[1];
    const float* W1 = (const float*)d_in[2];
    const float* b1 = (const float*)d_in[3];
    const float* W2 = (const float*)d_in[4];
    const float* b2 = (const float*)d_in[5];
    const float* W3 = (const float*)d_in[6];
    const float* b3 = (const float*)d_in[7];
    float* out = (float*)d_out;

    const int smem1 = (4*64*LDW + 2*64*LDW1 + 2*32*LDXP + 2*8*LDXP) * 4 + 3*64*4;
    cudaFuncSetAttribute(qvk_kernel, cudaFuncAttributeMaxDynamicSharedMemorySize, smem1);
    qvk_kernel<<<dim3(128, 16), 512, smem1>>>(x, e, W1, b1, W2, b2, W3, b3);

    const int smem2 = (4*128*LDP) * 4 + 2*512*4;
    cudaFuncSetAttribute(attn_kernel, cudaFuncAttributeMaxDynamicSharedMemorySize, smem2);
    attn_kernel<<<NTOT, 1024, smem2>>>(out);
}

// round 12
// speedup vs baseline: 1.6848x; 1.1276x over previous
#include <cuda_runtime.h>
#include <cstdint>

#define HW_ (128*128)
#define NTOT (16*64)
#define HWP (HW_/2)

__device__ uint32_t g_Qh[NTOT * HWP];
__device__ uint32_t g_Ql[NTOT * HWP];
__device__ uint32_t g_Vh[NTOT * HWP];
__device__ uint32_t g_Vl[NTOT * HWP];
__device__ float    g_K [NTOT * HW_];

// ---- bf16x3 helpers ---------------------------------------------------------
__device__ __forceinline__ void mma_bf16(float c[4], const uint32_t a[4],
                                         const uint32_t b0, const uint32_t b1) {
    asm volatile(
        "mma.sync.aligned.m16n8k16.row.col.f32.bf16.bf16.f32 "
        "{%0,%1,%2,%3}, {%4,%5,%6,%7}, {%8,%9}, {%0,%1,%2,%3};"
        : "+f"(c[0]), "+f"(c[1]), "+f"(c[2]), "+f"(c[3])
        : "r"(a[0]), "r"(a[1]), "r"(a[2]), "r"(a[3]), "r"(b0), "r"(b1));
}

__device__ __forceinline__ void bf16x2_split(float x, float y,
                                             uint32_t& hi2, uint32_t& lo2) {
    uint32_t h;
    asm("cvt.rn.bf16x2.f32 %0, %1, %2;" : "=r"(h) : "f"(y), "f"(x));
    float xh = __uint_as_float(h << 16);
    float yh = __uint_as_float(h & 0xffff0000u);
    float xl = x - xh;
    float yl = y - yh;
    hi2 = h;
    asm("cvt.rn.bf16x2.f32 %0, %1, %2;" : "=r"(lo2) : "f"(yl), "f"(xl));
}

__device__ __forceinline__ void ldsm_x4(uint32_t r[4], uint32_t addr) {
    asm volatile(
        "ldmatrix.sync.aligned.m8n8.x4.shared.b16 {%0,%1,%2,%3}, [%4];"
        : "=r"(r[0]), "=r"(r[1]), "=r"(r[2]), "=r"(r[3]) : "r"(addr));
}

// ---------------------------------------------------------------------------
// Kernel 1: fused 1x1-conv projections (R11 version, unchanged).
// ---------------------------------------------------------------------------
#define LDW  36
#define LDW1 12
#define LDXP 132

__global__ __launch_bounds__(512) void qvk_kernel(
    const float* __restrict__ x, const float* __restrict__ e,
    const float* __restrict__ W1, const float* __restrict__ b1,
    const float* __restrict__ W2, const float* __restrict__ b2,
    const float* __restrict__ W3, const float* __restrict__ b3)
{
    extern __shared__ uint32_t smu[];
    uint32_t* W2h = smu;
    uint32_t* W2l = W2h + 64*LDW;
    uint32_t* W3h = W2l + 64*LDW;
    uint32_t* W3l = W3h + 64*LDW;
    uint32_t* W1h = W3l + 64*LDW;
    uint32_t* W1l = W1h + 64*LDW1;
    uint32_t* Xh  = W1l + 64*LDW1;
    uint32_t* Xl  = Xh + 32*LDXP;
    uint32_t* Eh  = Xl + 32*LDXP;
    uint32_t* El  = Eh + 8*LDXP;
    float* b1s = (float*)(El + 8*LDXP);
    float* b2s = b1s + 64;
    float* b3s = b2s + 64;

    const int tid  = threadIdx.x;
    const int b    = blockIdx.y;
    const int pblk = blockIdx.x * 128;

    for (int idx = tid; idx < 2048; idx += 512) {
        int o = idx >> 5, p = idx & 31, c = 2*p;
        uint32_t h, l;
        bf16x2_split(W2[o*64 + c], W2[o*64 + c + 1], h, l);
        W2h[o*LDW + p] = h; W2l[o*LDW + p] = l;
        bf16x2_split(W3[o*64 + c], W3[o*64 + c + 1], h, l);
        W3h[o*LDW + p] = h; W3l[o*LDW + p] = l;
    }
    if (tid < 512) {
        int o = tid >> 3, p = tid & 7, c = 2*p;
        uint32_t h, l;
        bf16x2_split(W1[o*16 + c], W1[o*16 + c + 1], h, l);
        W1h[o*LDW1 + p] = h; W1l[o*LDW1 + p] = l;
    }
    if (tid < 64) { b1s[tid] = b1[tid]; b2s[tid] = b2[tid]; b3s[tid] = b3[tid]; }

    const float* xb = x + b*64*HW_ + pblk;
    const float* eb = e + b*16*HW_ + pblk;
    for (int idx = tid; idx < 32*128; idx += 512) {
        int cp = idx >> 7, p = idx & 127;
        uint32_t h, l;
        bf16x2_split(xb[(2*cp)*HW_ + p], xb[(2*cp+1)*HW_ + p], h, l);
        Xh[cp*LDXP + p] = h; Xl[cp*LDXP + p] = l;
    }
    for (int idx = tid; idx < 8*128; idx += 512) {
        int cp = idx >> 7, p = idx & 127;
        uint32_t h, l;
        bf16x2_split(eb[(2*cp)*HW_ + p], eb[(2*cp+1)*HW_ + p], h, l);
        Eh[cp*LDXP + p] = h; El[cp*LDXP + p] = l;
    }
    __syncthreads();

    const int warp = tid >> 5;
    const int lane = tid & 31;
    const int g4 = lane >> 2;
    const int tg = lane & 3;
    const int wb = warp & 7;
    const int wh = warp >> 3;
    const int p0 = wb*16;
    const int o0 = wh*32;

    float accV[2][2][4], accK[2][2][4], accQ[2][2][4];
    #pragma unroll
    for (int mt = 0; mt < 2; mt++) {
        int r = o0 + mt*16 + g4;
        float v0 = b2s[r], v1 = b2s[r+8];
        float k0 = b3s[r], k1 = b3s[r+8];
        float q0 = b1s[r], q1 = b1s[r+8];
        #pragma unroll
        for (int ntl = 0; ntl < 2; ntl++) {
            accV[mt][ntl][0] = v0; accV[mt][ntl][1] = v0;
            accV[mt][ntl][2] = v1; accV[mt][ntl][3] = v1;
            accK[mt][ntl][0] = k0; accK[mt][ntl][1] = k0;
            accK[mt][ntl][2] = k1; accK[mt][ntl][3] = k1;
            accQ[mt][ntl][0] = q0; accQ[mt][ntl][1] = q0;
            accQ[mt][ntl][2] = q1; accQ[mt][ntl][3] = q1;
        }
    }

    #pragma unroll
    for (int ks = 0; ks < 4; ks++) {
        uint32_t bh[2][2], bl[2][2];
        #pragma unroll
        for (int ntl = 0; ntl < 2; ntl++) {
            int pcol = p0 + ntl*8 + g4;
            bh[ntl][0] = Xh[(8*ks + tg)*LDXP + pcol];
            bl[ntl][0] = Xl[(8*ks + tg)*LDXP + pcol];
            bh[ntl][1] = Xh[(8*ks + tg + 4)*LDXP + pcol];
            bl[ntl][1] = Xl[(8*ks + tg + 4)*LDXP + pcol];
        }
        #pragma unroll
        for (int mt = 0; mt < 2; mt++) {
            const int rb = (o0 + mt*16 + g4)*LDW + 8*ks + tg;
            uint32_t ah[4], al[4];
            ah[0] = W2h[rb];           al[0] = W2l[rb];
            ah[1] = W2h[rb + 8*LDW];   al[1] = W2l[rb + 8*LDW];
            ah[2] = W2h[rb + 4];       al[2] = W2l[rb + 4];
            ah[3] = W2h[rb + 8*LDW+4]; al[3] = W2l[rb + 8*LDW+4];
            #pragma unroll
            for (int ntl = 0; ntl < 2; ntl++) {
                mma_bf16(accV[mt][ntl], ah, bh[ntl][0], bh[ntl][1]);
                mma_bf16(accV[mt][ntl], al, bh[ntl][0], bh[ntl][1]);
                mma_bf16(accV[mt][ntl], ah, bl[ntl][0], bl[ntl][1]);
            }
            ah[0] = W3h[rb];           al[0] = W3l[rb];
            ah[1] = W3h[rb + 8*LDW];   al[1] = W3l[rb + 8*LDW];
            ah[2] = W3h[rb + 4];       al[2] = W3l[rb + 4];
            ah[3] = W3h[rb + 8*LDW+4]; al[3] = W3l[rb + 8*LDW+4];
            #pragma unroll
            for (int ntl = 0; ntl < 2; ntl++) {
                mma_bf16(accK[mt][ntl], ah, bh[ntl][0], bh[ntl][1]);
                mma_bf16(accK[mt][ntl], al, bh[ntl][0], bh[ntl][1]);
                mma_bf16(accK[mt][ntl], ah, bl[ntl][0], bl[ntl][1]);
            }
        }
    }

    {
        uint32_t bh[2][2], bl[2][2];
        #pragma unroll
        for (int ntl = 0; ntl < 2; ntl++) {
            int pcol = p0 + ntl*8 + g4;
            bh[ntl][0] = Eh[tg*LDXP + pcol];
            bl[ntl][0] = El[tg*LDXP + pcol];
            bh[ntl][1] = Eh[(tg+4)*LDXP + pcol];
            bl[ntl][1] = El[(tg+4)*LDXP + pcol];
        }
        #pragma unroll
        for (int mt = 0; mt < 2; mt++) {
            const int rb = (o0 + mt*16 + g4)*LDW1 + tg;
            uint32_t ah[4], al[4];
            ah[0] = W1h[rb];            al[0] = W1l[rb];
            ah[1] = W1h[rb + 8*LDW1];   al[1] = W1l[rb + 8*LDW1];
            ah[2] = W1h[rb + 4];        al[2] = W1l[rb + 4];
            ah[3] = W1h[rb + 8*LDW1+4]; al[3] = W1l[rb + 8*LDW1+4];
            #pragma unroll
            for (int ntl = 0; ntl < 2; ntl++) {
                mma_bf16(accQ[mt][ntl], ah, bh[ntl][0], bh[ntl][1]);
                mma_bf16(accQ[mt][ntl], al, bh[ntl][0], bh[ntl][1]);
                mma_bf16(accQ[mt][ntl], ah, bl[ntl][0], bl[ntl][1]);
            }
        }
    }

    #pragma unroll
    for (int mt = 0; mt < 2; mt++) {
        int r = o0 + mt*16 + g4;
        #pragma unroll
        for (int ntl = 0; ntl < 2; ntl++) {
            int pc = pblk + p0 + ntl*8 + 2*tg;
            int pq = pc >> 1;
            int n0 = b*64 + r, n1 = n0 + 8;
            uint32_t h, l;
            bf16x2_split(accQ[mt][ntl][0], accQ[mt][ntl][1], h, l);
            g_Qh[n0*HWP + pq] = h; g_Ql[n0*HWP + pq] = l;
            bf16x2_split(accQ[mt][ntl][2], accQ[mt][ntl][3], h, l);
            g_Qh[n1*HWP + pq] = h; g_Ql[n1*HWP + pq] = l;
            bf16x2_split(accV[mt][ntl][0], accV[mt][ntl][1], h, l);
            g_Vh[n0*HWP + pq] = h; g_Vl[n0*HWP + pq] = l;
            bf16x2_split(accV[mt][ntl][2], accV[mt][ntl][3], h, l);
            g_Vh[n1*HWP + pq] = h; g_Vl[n1*HWP + pq] = l;
            *(float2*)&g_K[n0*HW_ + pc] = make_float2(accK[mt][ntl][0], accK[mt][ntl][1]);
            *(float2*)&g_K[n1*HW_ + pc] = make_float2(accK[mt][ntl][2], accK[mt][ntl][3]);
        }
    }
}

// ---------------------------------------------------------------------------
// Kernel 2: per-head attention, bf16x3 + ldmatrix fragment loads, 1024 thr.
// A-buf: Qp -> Pp ([128][LDP] k-pairs). B-buf: Vp [128][LDP] -> Kp [64][LDKP].
// ---------------------------------------------------------------------------
#define LDP 68
#define LDKP 136
#define HL_OFF (128*LDP*4)   // byte offset Ah->Al (and Bh->Bl)

__global__ __launch_bounds__(1024) void attn_kernel(float* __restrict__ out)
{
    extern __shared__ uint32_t smu[];
    uint32_t* Ah = smu;                  // [128][LDP]
    uint32_t* Al = Ah + 128*LDP;
    uint32_t* Bh = Al + 128*LDP;         // Vp [128][LDP] / Kp [64][LDKP]
    uint32_t* Bl = Bh + 128*LDP;
    float* redM = (float*)(Bl + 128*LDP);  // [4][128]
    float* redS = redM + 512;              // [4][128]

    const int tid  = threadIdx.x;
    const int warp = tid >> 5;
    const int lane = tid & 31;
    const int wb   = warp & 7;
    const int wq   = warp >> 3;
    const int n    = blockIdx.x;
    const uint32_t* Qh = g_Qh + n*HWP;
    const uint32_t* Ql = g_Ql + n*HWP;
    const uint32_t* Vh = g_Vh + n*HWP;
    const uint32_t* Vl = g_Vl + n*HWP;
    const float*    K  = g_K  + n*HW_;

    for (int idx = tid; idx < HWP; idx += 1024) {
        int r = idx >> 6, c = idx & 63;
        Ah[r*LDP + c] = Qh[idx];
        Al[r*LDP + c] = Ql[idx];
        Bh[r*LDP + c] = Vh[idx];
        Bl[r*LDP + c] = Vl[idx];
    }
    __syncthreads();

    const int g4 = lane >> 2;
    const int tg = lane & 3;
    const int r0 = wb*16 + g4;
    const int nt0 = wq*4;

    // ldmatrix lane addresses
    const int rowA = wb*16 + ((lane >> 3) & 1)*8 + (lane & 7);
    const int colA = (lane >> 4)*4;
    const uint32_t adrA =
        (uint32_t)__cvta_generic_to_shared(&Ah[rowA*LDP + colA]);
    const int tile  = lane >> 3;
    const int rowB0 = (nt0 + (tile >> 1))*8 + (lane & 7);
    const int rowB1 = (nt0 + 2 + (tile >> 1))*8 + (lane & 7);
    const int colB  = (tile & 1)*4;
    const uint32_t adrB0 =
        (uint32_t)__cvta_generic_to_shared(&Bh[rowB0*LDP + colB]);
    const uint32_t adrB1 =
        (uint32_t)__cvta_generic_to_shared(&Bh[rowB1*LDP + colB]);

    float acc[4][4];
    #pragma unroll
    for (int j = 0; j < 4; j++)
        #pragma unroll
        for (int i = 0; i < 4; i++) acc[j][i] = 0.0f;

    // ---- Phase A: S = Q @ V^T (8 k16 steps, LDSM-fed)
    #pragma unroll 2
    for (int k = 0; k < 8; k++) {
        const uint32_t koff = k*32;   // 8 u32 per k16 step
        uint32_t ah[4], al[4], b0h[4], b0l[4], b1h[4], b1l[4];
        ldsm_x4(ah, adrA + koff);
        ldsm_x4(al, adrA + koff + HL_OFF);
        ldsm_x4(b0h, adrB0 + koff);
        ldsm_x4(b0l, adrB0 + koff + HL_OFF);
        ldsm_x4(b1h, adrB1 + koff);
        ldsm_x4(b1l, adrB1 + koff + HL_OFF);
        mma_bf16(acc[0], ah, b0h[0], b0h[1]);
        mma_bf16(acc[0], al, b0h[0], b0h[1]);
        mma_bf16(acc[0], ah, b0l[0], b0l[1]);
        mma_bf16(acc[1], ah, b0h[2], b0h[3]);
        mma_bf16(acc[1], al, b0h[2], b0h[3]);
        mma_bf16(acc[1], ah, b0l[2], b0l[3]);
        mma_bf16(acc[2], ah, b1h[0], b1h[1]);
        mma_bf16(acc[2], al, b1h[0], b1h[1]);
        mma_bf16(acc[2], ah, b1l[0], b1l[1]);
        mma_bf16(acc[3], ah, b1h[2], b1h[3]);
        mma_bf16(acc[3], al, b1h[2], b1h[3]);
        mma_bf16(acc[3], ah, b1l[2], b1l[3]);
    }

    // ---- Softmax (4-warp row groups)
    float m1 = -1e30f, m2 = -1e30f;
    #pragma unroll
    for (int j = 0; j < 4; j++) {
        m1 = fmaxf(m1, fmaxf(acc[j][0], acc[j][1]));
        m2 = fmaxf(m2, fmaxf(acc[j][2], acc[j][3]));
    }
    #pragma unroll
    for (int off = 1; off < 4; off <<= 1) {
        m1 = fmaxf(m1, __shfl_xor_sync(0xFFFFFFFFu, m1, off));
        m2 = fmaxf(m2, __shfl_xor_sync(0xFFFFFFFFu, m2, off));
    }
    if (tg == 0) {
        redM[wq*128 + r0]     = m1;
        redM[wq*128 + r0 + 8] = m2;
    }
    __syncthreads();

    const float gm1 = fmaxf(fmaxf(redM[r0],       redM[128 + r0]),
                            fmaxf(redM[256 + r0], redM[384 + r0]));
    const float gm2 = fmaxf(fmaxf(redM[r0+8],       redM[128 + r0+8]),
                            fmaxf(redM[256 + r0+8], redM[384 + r0+8]));

    float s1 = 0.0f, s2 = 0.0f;
    #pragma unroll
    for (int j = 0; j < 4; j++) {
        acc[j][0] = __expf(acc[j][0] - gm1);
        acc[j][1] = __expf(acc[j][1] - gm1);
        acc[j][2] = __expf(acc[j][2] - gm2);
        acc[j][3] = __expf(acc[j][3] - gm2);
        s1 += acc[j][0] + acc[j][1];
        s2 += acc[j][2] + acc[j][3];
    }
    #pragma unroll
    for (int off = 1; off < 4; off <<= 1) {
        s1 += __shfl_xor_sync(0xFFFFFFFFu, s1, off);
        s2 += __shfl_xor_sync(0xFFFFFFFFu, s2, off);
    }
    if (tg == 0) {
        redS[wq*128 + r0]     = s1;
        redS[wq*128 + r0 + 8] = s2;
    }

    // Store P split into A-buf (each thread's acc pair = one k-pair)
    #pragma unroll
    for (int j = 0; j < 4; j++) {
        const int pb = (nt0 + j)*4 + tg;
        uint32_t h, l;
        bf16x2_split(acc[j][0], acc[j][1], h, l);
        Ah[r0*LDP + pb] = h; Al[r0*LDP + pb] = l;
        bf16x2_split(acc[j][2], acc[j][3], h, l);
        Ah[(r0+8)*LDP + pb] = h; Al[(r0+8)*LDP + pb] = l;
    }
    // Stage K vertical pairs: Kp[gp][w] = pack(K[2gp][w], K[2gp+1][w])
    for (int idx = tid; idx < 64*128; idx += 1024) {
        int gp = idx >> 7, w = idx & 127;
        uint32_t h, l;
        bf16x2_split(K[(2*gp)*128 + w], K[(2*gp+1)*128 + w], h, l);
        Bh[gp*LDKP + w] = h; Bl[gp*LDKP + w] = l;
    }
    __syncthreads();

    const float inv1 = 1.0f / (redS[r0] + redS[128 + r0] +
                               redS[256 + r0] + redS[384 + r0]);
    const float inv2 = 1.0f / (redS[r0+8] + redS[128 + r0+8] +
                               redS[256 + r0+8] + redS[384 + r0+8]);

    // ---- Phase C: ctx = P @ K (A via LDSM, B scalar but conflict-free)
    float oac[4][4];
    #pragma unroll
    for (int j = 0; j < 4; j++)
        #pragma unroll
        for (int i = 0; i < 4; i++) oac[j][i] = 0.0f;

    #pragma unroll 2
    for (int k = 0; k < 8; k++) {
        const int kp = k*8 + tg;
        uint32_t ah[4], al[4];
        ldsm_x4(ah, adrA + k*32);
        ldsm_x4(al, adrA + k*32 + HL_OFF);
        #pragma unroll
        for (int j = 0; j < 4; j++) {
            const int nc = (nt0 + j)*8 + g4;
            uint32_t bh0 = Bh[kp*LDKP + nc],     bl0 = Bl[kp*LDKP + nc];
            uint32_t bh1 = Bh[(kp+4)*LDKP + nc], bl1 = Bl[(kp+4)*LDKP + nc];
            mma_bf16(oac[j], ah, bh0, bh1);
            mma_bf16(oac[j], al, bh0, bh1);
            mma_bf16(oac[j], ah, bl0, bl1);
        }
    }

    // Epilogue
    #pragma unroll
    for (int j = 0; j < 4; j++) {
        const int cb = (nt0 + j)*8 + 2*tg;
        *(float2*)&out[n*HW_ + r0*128 + cb] =
            make_float2(oac[j][0]*inv1, oac[j][1]*inv1);
        *(float2*)&out[n*HW_ + (r0+8)*128 + cb] =
            make_float2(oac[j][2]*inv2, oac[j][3]*inv2);
    }
}

// ---------------------------------------------------------------------------
extern "C" void kernel_launch(void* const* d_in, const int* in_sizes, int n_in,
                              void* d_out, int out_size)
{
    const float* x  = (const float*)d_in[0];
    const float* e  = (const float*)d_in[1];
    const float* W1 = (const float*)d_in[2];
    const float* b1 = (const float*)d_in[3];
    const float* W2 = (const float*)d_in[4];
    const float* b2 = (const float*)d_in[5];
    const float* W3 = (const float*)d_in[6];
    const float* b3 = (const float*)d_in[7];
    float* out = (float*)d_out;

    const int smem1 = (4*64*LDW + 2*64*LDW1 + 2*32*LDXP + 2*8*LDXP) * 4 + 3*64*4;
    cudaFuncSetAttribute(qvk_kernel, cudaFuncAttributeMaxDynamicSharedMemorySize, smem1);
    qvk_kernel<<<dim3(128, 16), 512, smem1>>>(x, e, W1, b1, W2, b2, W3, b3);

    const int smem2 = (4*128*LDP) * 4 + 2*512*4;
    cudaFuncSetAttribute(attn_kernel, cudaFuncAttributeMaxDynamicSharedMemorySize, smem2);
    attn_kernel<<<NTOT, 1024, smem2>>>(out);
}

// round 13
// speedup vs baseline: 1.6919x; 1.0042x over previous
#include <cuda_runtime.h>
#include <cstdint>

#define HW_ (128*128)
#define NTOT (16*64)
#define HWP (HW_/2)

__device__ uint32_t g_Qh[NTOT * HWP];
__device__ uint32_t g_Ql[NTOT * HWP];
__device__ uint32_t g_Vh[NTOT * HWP];
__device__ uint32_t g_Vl[NTOT * HWP];
__device__ float    g_K [NTOT * HW_];

// ---- bf16x3 helpers ---------------------------------------------------------
__device__ __forceinline__ void mma_bf16(float c[4], const uint32_t a[4],
                                         const uint32_t b0, const uint32_t b1) {
    asm volatile(
        "mma.sync.aligned.m16n8k16.row.col.f32.bf16.bf16.f32 "
        "{%0,%1,%2,%3}, {%4,%5,%6,%7}, {%8,%9}, {%0,%1,%2,%3};"
        : "+f"(c[0]), "+f"(c[1]), "+f"(c[2]), "+f"(c[3])
        : "r"(a[0]), "r"(a[1]), "r"(a[2]), "r"(a[3]), "r"(b0), "r"(b1));
}

__device__ __forceinline__ void bf16x2_split(float x, float y,
                                             uint32_t& hi2, uint32_t& lo2) {
    uint32_t h;
    asm("cvt.rn.bf16x2.f32 %0, %1, %2;" : "=r"(h) : "f"(y), "f"(x));
    float xh = __uint_as_float(h << 16);
    float yh = __uint_as_float(h & 0xffff0000u);
    float xl = x - xh;
    float yl = y - yh;
    hi2 = h;
    asm("cvt.rn.bf16x2.f32 %0, %1, %2;" : "=r"(lo2) : "f"(yl), "f"(xl));
}

__device__ __forceinline__ void ldsm_x4(uint32_t r[4], uint32_t addr) {
    asm volatile(
        "ldmatrix.sync.aligned.m8n8.x4.shared.b16 {%0,%1,%2,%3}, [%4];"
        : "=r"(r[0]), "=r"(r[1]), "=r"(r[2]), "=r"(r[3]) : "r"(addr));
}

// ---------------------------------------------------------------------------
// Kernel 1: fused 1x1-conv projections, bf16x3, fully LDSM-fed mainloop.
// 512 thr / 16 warps; ~93KB smem (2 CTAs/SM).
// W: [o][cpair] stride 36 (W1: 12). X/E: pixel-major [p][cpair] stride 36/12.
// ---------------------------------------------------------------------------
#define LDW  36
#define LDW1 12
#define WHL  (64*LDW*4)    // byte offset Wh->Wl
#define W1HL (64*LDW1*4)
#define XHL  (128*LDW*4)   // byte offset Xph->Xpl
#define EHL  (128*LDW1*4)

__global__ __launch_bounds__(512) void qvk_kernel(
    const float* __restrict__ x, const float* __restrict__ e,
    const float* __restrict__ W1, const float* __restrict__ b1,
    const float* __restrict__ W2, const float* __restrict__ b2,
    const float* __restrict__ W3, const float* __restrict__ b3)
{
    extern __shared__ uint32_t smu[];
    uint32_t* W2h = smu;                 // [64][36] + [64][36] lo
    uint32_t* W2l = W2h + 64*LDW;
    uint32_t* W3h = W2l + 64*LDW;
    uint32_t* W3l = W3h + 64*LDW;
    uint32_t* W1h = W3l + 64*LDW;        // [64][12] + lo
    uint32_t* W1l = W1h + 64*LDW1;
    uint32_t* Xph = W1l + 64*LDW1;       // [128][36] + lo (pixel-major pairs)
    uint32_t* Xpl = Xph + 128*LDW;
    uint32_t* Eph = Xpl + 128*LDW;       // [128][12] + lo
    uint32_t* Epl = Eph + 128*LDW1;
    float* b1s = (float*)(Epl + 128*LDW1);
    float* b2s = b1s + 64;
    float* b3s = b2s + 64;

    const int tid  = threadIdx.x;
    const int b    = blockIdx.y;
    const int pblk = blockIdx.x * 128;

    // Pre-split weights (pairs along c)
    for (int idx = tid; idx < 2048; idx += 512) {
        int o = idx >> 5, p = idx & 31, c = 2*p;
        uint32_t h, l;
        bf16x2_split(W2[o*64 + c], W2[o*64 + c + 1], h, l);
        W2h[o*LDW + p] = h; W2l[o*LDW + p] = l;
        bf16x2_split(W3[o*64 + c], W3[o*64 + c + 1], h, l);
        W3h[o*LDW + p] = h; W3l[o*LDW + p] = l;
    }
    if (tid < 512) {
        int o = tid >> 3, p = tid & 7, c = 2*p;
        uint32_t h, l;
        bf16x2_split(W1[o*16 + c], W1[o*16 + c + 1], h, l);
        W1h[o*LDW1 + p] = h; W1l[o*LDW1 + p] = l;
    }
    if (tid < 64) { b1s[tid] = b1[tid]; b2s[tid] = b2[tid]; b3s[tid] = b3[tid]; }

    // Stage X/E pixel-major with channel pairs: Xp[p][cp] = pack(x[2cp][p], x[2cp+1][p])
    const float* xb = x + b*64*HW_ + pblk;
    const float* eb = e + b*16*HW_ + pblk;
    for (int idx = tid; idx < 32*128; idx += 512) {
        int cp = idx >> 7, p = idx & 127;
        uint32_t h, l;
        bf16x2_split(xb[(2*cp)*HW_ + p], xb[(2*cp+1)*HW_ + p], h, l);
        Xph[p*LDW + cp] = h; Xpl[p*LDW + cp] = l;
    }
    for (int idx = tid; idx < 8*128; idx += 512) {
        int cp = idx >> 7, p = idx & 127;
        uint32_t h, l;
        bf16x2_split(eb[(2*cp)*HW_ + p], eb[(2*cp+1)*HW_ + p], h, l);
        Eph[p*LDW1 + cp] = h; Epl[p*LDW1 + cp] = l;
    }
    __syncthreads();

    const int warp = tid >> 5;
    const int lane = tid & 31;
    const int g4 = lane >> 2;
    const int tg = lane & 3;
    const int wb = warp & 7;
    const int wh = warp >> 3;
    const int p0 = wb*16;
    const int o0 = wh*32;

    // ldmatrix lane addresses
    const int arow = ((lane >> 3) & 1)*8 + (lane & 7);
    const int acol = (lane >> 4)*4;
    const uint32_t adrW2_0 = (uint32_t)__cvta_generic_to_shared(
        &W2h[(o0 + arow)*LDW + acol]);
    const uint32_t adrW2_1 = (uint32_t)__cvta_generic_to_shared(
        &W2h[(o0 + 16 + arow)*LDW + acol]);
    const uint32_t adrW3_0 = (uint32_t)__cvta_generic_to_shared(
        &W3h[(o0 + arow)*LDW + acol]);
    const uint32_t adrW3_1 = (uint32_t)__cvta_generic_to_shared(
        &W3h[(o0 + 16 + arow)*LDW + acol]);
    const uint32_t adrW1_0 = (uint32_t)__cvta_generic_to_shared(
        &W1h[(o0 + arow)*LDW1 + acol]);
    const uint32_t adrW1_1 = (uint32_t)__cvta_generic_to_shared(
        &W1h[(o0 + 16 + arow)*LDW1 + acol]);
    const int btile = lane >> 3;
    const int brow  = p0 + (btile >> 1)*8 + (lane & 7);
    const int bcol  = (btile & 1)*4;
    const uint32_t adrX = (uint32_t)__cvta_generic_to_shared(
        &Xph[brow*LDW + bcol]);
    const uint32_t adrE = (uint32_t)__cvta_generic_to_shared(
        &Eph[brow*LDW1 + bcol]);

    float accV[2][2][4], accK[2][2][4], accQ[2][2][4];
    #pragma unroll
    for (int mt = 0; mt < 2; mt++) {
        int r = o0 + mt*16 + g4;
        float v0 = b2s[r], v1 = b2s[r+8];
        float k0 = b3s[r], k1 = b3s[r+8];
        float q0 = b1s[r], q1 = b1s[r+8];
        #pragma unroll
        for (int ntl = 0; ntl < 2; ntl++) {
            accV[mt][ntl][0] = v0; accV[mt][ntl][1] = v0;
            accV[mt][ntl][2] = v1; accV[mt][ntl][3] = v1;
            accK[mt][ntl][0] = k0; accK[mt][ntl][1] = k0;
            accK[mt][ntl][2] = k1; accK[mt][ntl][3] = k1;
            accQ[mt][ntl][0] = q0; accQ[mt][ntl][1] = q0;
            accQ[mt][ntl][2] = q1; accQ[mt][ntl][3] = q1;
        }
    }

    // ---- V, K over C=64: 4 k16 steps, all LDSM
    #pragma unroll
    for (int ks = 0; ks < 4; ks++) {
        const uint32_t ko = ks*32;   // 8 u32 per k16 step
        uint32_t bxh[4], bxl[4];
        ldsm_x4(bxh, adrX + ko);
        ldsm_x4(bxl, adrX + ko + XHL);
        #pragma unroll
        for (int mt = 0; mt < 2; mt++) {
            const uint32_t aw2 = (mt ? adrW2_1 : adrW2_0) + ko;
            const uint32_t aw3 = (mt ? adrW3_1 : adrW3_0) + ko;
            uint32_t a2h[4], a2l[4], a3h[4], a3l[4];
            ldsm_x4(a2h, aw2);
            ldsm_x4(a2l, aw2 + WHL);
            ldsm_x4(a3h, aw3);
            ldsm_x4(a3l, aw3 + WHL);
            mma_bf16(accV[mt][0], a2h, bxh[0], bxh[1]);
            mma_bf16(accV[mt][0], a2l, bxh[0], bxh[1]);
            mma_bf16(accV[mt][0], a2h, bxl[0], bxl[1]);
            mma_bf16(accV[mt][1], a2h, bxh[2], bxh[3]);
            mma_bf16(accV[mt][1], a2l, bxh[2], bxh[3]);
            mma_bf16(accV[mt][1], a2h, bxl[2], bxl[3]);
            mma_bf16(accK[mt][0], a3h, bxh[0], bxh[1]);
            mma_bf16(accK[mt][0], a3l, bxh[0], bxh[1]);
            mma_bf16(accK[mt][0], a3h, bxl[0], bxl[1]);
            mma_bf16(accK[mt][1], a3h, bxh[2], bxh[3]);
            mma_bf16(accK[mt][1], a3l, bxh[2], bxh[3]);
            mma_bf16(accK[mt][1], a3h, bxl[2], bxl[3]);
        }
    }

    // ---- Q over C1=16: 1 k16 step
    {
        uint32_t beh[4], bel[4];
        ldsm_x4(beh, adrE);
        ldsm_x4(bel, adrE + EHL);
        #pragma unroll
        for (int mt = 0; mt < 2; mt++) {
            const uint32_t aw1 = mt ? adrW1_1 : adrW1_0;
            uint32_t a1h[4], a1l[4];
            ldsm_x4(a1h, aw1);
            ldsm_x4(a1l, aw1 + W1HL);
            mma_bf16(accQ[mt][0], a1h, beh[0], beh[1]);
            mma_bf16(accQ[mt][0], a1l, beh[0], beh[1]);
            mma_bf16(accQ[mt][0], a1h, bel[0], bel[1]);
            mma_bf16(accQ[mt][1], a1h, beh[2], beh[3]);
            mma_bf16(accQ[mt][1], a1l, beh[2], beh[3]);
            mma_bf16(accQ[mt][1], a1h, bel[2], bel[3]);
        }
    }

    // ---- Store: Q,V packed (pixel pairs); K fp32
    #pragma unroll
    for (int mt = 0; mt < 2; mt++) {
        int r = o0 + mt*16 + g4;
        #pragma unroll
        for (int ntl = 0; ntl < 2; ntl++) {
            int pc = pblk + p0 + ntl*8 + 2*tg;
            int pq = pc >> 1;
            int n0 = b*64 + r, n1 = n0 + 8;
            uint32_t h, l;
            bf16x2_split(accQ[mt][ntl][0], accQ[mt][ntl][1], h, l);
            g_Qh[n0*HWP + pq] = h; g_Ql[n0*HWP + pq] = l;
            bf16x2_split(accQ[mt][ntl][2], accQ[mt][ntl][3], h, l);
            g_Qh[n1*HWP + pq] = h; g_Ql[n1*HWP + pq] = l;
            bf16x2_split(accV[mt][ntl][0], accV[mt][ntl][1], h, l);
            g_Vh[n0*HWP + pq] = h; g_Vl[n0*HWP + pq] = l;
            bf16x2_split(accV[mt][ntl][2], accV[mt][ntl][3], h, l);
            g_Vh[n1*HWP + pq] = h; g_Vl[n1*HWP + pq] = l;
            *(float2*)&g_K[n0*HW_ + pc] = make_float2(accK[mt][ntl][0], accK[mt][ntl][1]);
            *(float2*)&g_K[n1*HW_ + pc] = make_float2(accK[mt][ntl][2], accK[mt][ntl][3]);
        }
    }
}

// ---------------------------------------------------------------------------
// Kernel 2: per-head attention (R12 winner, unchanged).
// ---------------------------------------------------------------------------
#define LDP 68
#define LDKP 136
#define HL_OFF (128*LDP*4)

__global__ __launch_bounds__(1024) void attn_kernel(float* __restrict__ out)
{
    extern __shared__ uint32_t smu[];
    uint32_t* Ah = smu;
    uint32_t* Al = Ah + 128*LDP;
    uint32_t* Bh = Al + 128*LDP;
    uint32_t* Bl = Bh + 128*LDP;
    float* redM = (float*)(Bl + 128*LDP);
    float* redS = redM + 512;

    const int tid  = threadIdx.x;
    const int warp = tid >> 5;
    const int lane = tid & 31;
    const int wb   = warp & 7;
    const int wq   = warp >> 3;
    const int n    = blockIdx.x;
    const uint32_t* Qh = g_Qh + n*HWP;
    const uint32_t* Ql = g_Ql + n*HWP;
    const uint32_t* Vh = g_Vh + n*HWP;
    const uint32_t* Vl = g_Vl + n*HWP;
    const float*    K  = g_K  + n*HW_;

    for (int idx = tid; idx < HWP; idx += 1024) {
        int r = idx >> 6, c = idx & 63;
        Ah[r*LDP + c] = Qh[idx];
        Al[r*LDP + c] = Ql[idx];
        Bh[r*LDP + c] = Vh[idx];
        Bl[r*LDP + c] = Vl[idx];
    }
    __syncthreads();

    const int g4 = lane >> 2;
    const int tg = lane & 3;
    const int r0 = wb*16 + g4;
    const int nt0 = wq*4;

    const int rowA = wb*16 + ((lane >> 3) & 1)*8 + (lane & 7);
    const int colA = (lane >> 4)*4;
    const uint32_t adrA =
        (uint32_t)__cvta_generic_to_shared(&Ah[rowA*LDP + colA]);
    const int tile  = lane >> 3;
    const int rowB0 = (nt0 + (tile >> 1))*8 + (lane & 7);
    const int rowB1 = (nt0 + 2 + (tile >> 1))*8 + (lane & 7);
    const int colB  = (tile & 1)*4;
    const uint32_t adrB0 =
        (uint32_t)__cvta_generic_to_shared(&Bh[rowB0*LDP + colB]);
    const uint32_t adrB1 =
        (uint32_t)__cvta_generic_to_shared(&Bh[rowB1*LDP + colB]);

    float acc[4][4];
    #pragma unroll
    for (int j = 0; j < 4; j++)
        #pragma unroll
        for (int i = 0; i < 4; i++) acc[j][i] = 0.0f;

    #pragma unroll 2
    for (int k = 0; k < 8; k++) {
        const uint32_t koff = k*32;
        uint32_t ah[4], al[4], b0h[4], b0l[4], b1h[4], b1l[4];
        ldsm_x4(ah, adrA + koff);
        ldsm_x4(al, adrA + koff + HL_OFF);
        ldsm_x4(b0h, adrB0 + koff);
        ldsm_x4(b0l, adrB0 + koff + HL_OFF);
        ldsm_x4(b1h, adrB1 + koff);
        ldsm_x4(b1l, adrB1 + koff + HL_OFF);
        mma_bf16(acc[0], ah, b0h[0], b0h[1]);
        mma_bf16(acc[0], al, b0h[0], b0h[1]);
        mma_bf16(acc[0], ah, b0l[0], b0l[1]);
        mma_bf16(acc[1], ah, b0h[2], b0h[3]);
        mma_bf16(acc[1], al, b0h[2], b0h[3]);
        mma_bf16(acc[1], ah, b0l[2], b0l[3]);
        mma_bf16(acc[2], ah, b1h[0], b1h[1]);
        mma_bf16(acc[2], al, b1h[0], b1h[1]);
        mma_bf16(acc[2], ah, b1l[0], b1l[1]);
        mma_bf16(acc[3], ah, b1h[2], b1h[3]);
        mma_bf16(acc[3], al, b1h[2], b1h[3]);
        mma_bf16(acc[3], ah, b1l[2], b1l[3]);
    }

    float m1 = -1e30f, m2 = -1e30f;
    #pragma unroll
    for (int j = 0; j < 4; j++) {
        m1 = fmaxf(m1, fmaxf(acc[j][0], acc[j][1]));
        m2 = fmaxf(m2, fmaxf(acc[j][2], acc[j][3]));
    }
    #pragma unroll
    for (int off = 1; off < 4; off <<= 1) {
        m1 = fmaxf(m1, __shfl_xor_sync(0xFFFFFFFFu, m1, off));
        m2 = fmaxf(m2, __shfl_xor_sync(0xFFFFFFFFu, m2, off));
    }
    if (tg == 0) {
        redM[wq*128 + r0]     = m1;
        redM[wq*128 + r0 + 8] = m2;
    }
    __syncthreads();

    const float gm1 = fmaxf(fmaxf(redM[r0],       redM[128 + r0]),
                            fmaxf(redM[256 + r0], redM[384 + r0]));
    const float gm2 = fmaxf(fmaxf(redM[r0+8],       redM[128 + r0+8]),
                            fmaxf(redM[256 + r0+8], redM[384 + r0+8]));

    float s1 = 0.0f, s2 = 0.0f;
    #pragma unroll
    for (int j = 0; j < 4; j++) {
        acc[j][0] = __expf(acc[j][0] - gm1);
        acc[j][1] = __expf(acc[j][1] - gm1);
        acc[j][2] = __expf(acc[j][2] - gm2);
        acc[j][3] = __expf(acc[j][3] - gm2);
        s1 += acc[j][0] + acc[j][1];
        s2 += acc[j][2] + acc[j][3];
    }
    #pragma unroll
    for (int off = 1; off < 4; off <<= 1) {
        s1 += __shfl_xor_sync(0xFFFFFFFFu, s1, off);
        s2 += __shfl_xor_sync(0xFFFFFFFFu, s2, off);
    }
    if (tg == 0) {
        redS[wq*128 + r0]     = s1;
        redS[wq*128 + r0 + 8] = s2;
    }

    #pragma unroll
    for (int j = 0; j < 4; j++) {
        const int pb = (nt0 + j)*4 + tg;
        uint32_t h, l;
        bf16x2_split(acc[j][0], acc[j][1], h, l);
        Ah[r0*LDP + pb] = h; Al[r0*LDP + pb] = l;
        bf16x2_split(acc[j][2], acc[j][3], h, l);
        Ah[(r0+8)*LDP + pb] = h; Al[(r0+8)*LDP + pb] = l;
    }
    for (int idx = tid; idx < 64*128; idx += 1024) {
        int gp = idx >> 7, w = idx & 127;
        uint32_t h, l;
        bf16x2_split(K[(2*gp)*128 + w], K[(2*gp+1)*128 + w], h, l);
        Bh[gp*LDKP + w] = h; Bl[gp*LDKP + w] = l;
    }
    __syncthreads();

    const float inv1 = 1.0f / (redS[r0] + redS[128 + r0] +
                               redS[256 + r0] + redS[384 + r0]);
    const float inv2 = 1.0f / (redS[r0+8] + redS[128 + r0+8] +
                               redS[256 + r0+8] + redS[384 + r0+8]);

    float oac[4][4];
    #pragma unroll
    for (int j = 0; j < 4; j++)
        #pragma unroll
        for (int i = 0; i < 4; i++) oac[j][i] = 0.0f;

    #pragma unroll 2
    for (int k = 0; k < 8; k++) {
        const int kp = k*8 + tg;
        uint32_t ah[4], al[4];
        ldsm_x4(ah, adrA + k*32);
        ldsm_x4(al, adrA + k*32 + HL_OFF);
        #pragma unroll
        for (int j = 0; j < 4; j++) {
            const int nc = (nt0 + j)*8 + g4;
            uint32_t bh0 = Bh[kp*LDKP + nc],     bl0 = Bl[kp*LDKP + nc];
            uint32_t bh1 = Bh[(kp+4)*LDKP + nc], bl1 = Bl[(kp+4)*LDKP + nc];
            mma_bf16(oac[j], ah, bh0, bh1);
            mma_bf16(oac[j], al, bh0, bh1);
            mma_bf16(oac[j], ah, bl0, bl1);
        }
    }

    #pragma unroll
    for (int j = 0; j < 4; j++) {
        const int cb = (nt0 + j)*8 + 2*tg;
        *(float2*)&out[n*HW_ + r0*128 + cb] =
            make_float2(oac[j][0]*inv1, oac[j][1]*inv1);
        *(float2*)&out[n*HW_ + (r0+8)*128 + cb] =
            make_float2(oac[j][2]*inv2, oac[j][3]*inv2);
    }
}

// ---------------------------------------------------------------------------
extern "C" void kernel_launch(void* const* d_in, const int* in_sizes, int n_in,
                              void* d_out, int out_size)
{
    const float* x  = (const float*)d_in[0];
    const float* e  = (const float*)d_in[1];
    const float* W1 = (const float*)d_in[2];
    const float* b1 = (const float*)d_in[3];
    const float* W2 = (const float*)d_in[4];
    const float* b2 = (const float*)d_in[5];
    const float* W3 = (const float*)d_in[6];
    const float* b3 = (const float*)d_in[7];
    float* out = (float*)d_out;

    const int smem1 = (4*64*LDW + 2*64*LDW1 + 2*128*LDW + 2*128*LDW1) * 4
                      + 3*64*4;
    cudaFuncSetAttribute(qvk_kernel, cudaFuncAttributeMaxDynamicSharedMemorySize, smem1);
    qvk_kernel<<<dim3(128, 16), 512, smem1>>>(x, e, W1, b1, W2, b2, W3, b3);

    const int smem2 = (4*128*LDP) * 4 + 2*512*4;
    cudaFuncSetAttribute(attn_kernel, cudaFuncAttributeMaxDynamicSharedMemorySize, smem2);
    attn_kernel<<<NTOT, 1024, smem2>>>(out);
}

// round 14
// speedup vs baseline: 1.7075x; 1.0092x over previous
#include <cuda_runtime.h>
#include <cstdint>

#define HW_ (128*128)
#define NTOT (16*64)
#define HWP (HW_/2)

__device__ uint32_t g_Qh[NTOT * HWP];
__device__ uint32_t g_Ql[NTOT * HWP];
__device__ uint32_t g_Vh[NTOT * HWP];
__device__ uint32_t g_Vl[NTOT * HWP];
__device__ float    g_K [NTOT * HW_];

// ---- bf16x3 helpers ---------------------------------------------------------
__device__ __forceinline__ void mma_bf16(float c[4], const uint32_t a[4],
                                         const uint32_t b0, const uint32_t b1) {
    asm volatile(
        "mma.sync.aligned.m16n8k16.row.col.f32.bf16.bf16.f32 "
        "{%0,%1,%2,%3}, {%4,%5,%6,%7}, {%8,%9}, {%0,%1,%2,%3};"
        : "+f"(c[0]), "+f"(c[1]), "+f"(c[2]), "+f"(c[3])
        : "r"(a[0]), "r"(a[1]), "r"(a[2]), "r"(a[3]), "r"(b0), "r"(b1));
}

__device__ __forceinline__ void bf16x2_split(float x, float y,
                                             uint32_t& hi2, uint32_t& lo2) {
    uint32_t h;
    asm("cvt.rn.bf16x2.f32 %0, %1, %2;" : "=r"(h) : "f"(y), "f"(x));
    float xh = __uint_as_float(h << 16);
    float yh = __uint_as_float(h & 0xffff0000u);
    float xl = x - xh;
    float yl = y - yh;
    hi2 = h;
    asm("cvt.rn.bf16x2.f32 %0, %1, %2;" : "=r"(lo2) : "f"(yl), "f"(xl));
}

__device__ __forceinline__ void ldsm_x4(uint32_t r[4], uint32_t addr) {
    asm volatile(
        "ldmatrix.sync.aligned.m8n8.x4.shared.b16 {%0,%1,%2,%3}, [%4];"
        : "=r"(r[0]), "=r"(r[1]), "=r"(r[2]), "=r"(r[3]) : "r"(addr));
}

// ---------------------------------------------------------------------------
// Kernel 1: fused 1x1-conv projections (R13 version, unchanged).
// ---------------------------------------------------------------------------
#define LDW  36
#define LDW1 12
#define WHL  (64*LDW*4)
#define W1HL (64*LDW1*4)
#define XHL  (128*LDW*4)
#define EHL  (128*LDW1*4)

__global__ __launch_bounds__(512) void qvk_kernel(
    const float* __restrict__ x, const float* __restrict__ e,
    const float* __restrict__ W1, const float* __restrict__ b1,
    const float* __restrict__ W2, const float* __restrict__ b2,
    const float* __restrict__ W3, const float* __restrict__ b3)
{
    extern __shared__ uint32_t smu[];
    uint32_t* W2h = smu;
    uint32_t* W2l = W2h + 64*LDW;
    uint32_t* W3h = W2l + 64*LDW;
    uint32_t* W3l = W3h + 64*LDW;
    uint32_t* W1h = W3l + 64*LDW;
    uint32_t* W1l = W1h + 64*LDW1;
    uint32_t* Xph = W1l + 64*LDW1;
    uint32_t* Xpl = Xph + 128*LDW;
    uint32_t* Eph = Xpl + 128*LDW;
    uint32_t* Epl = Eph + 128*LDW1;
    float* b1s = (float*)(Epl + 128*LDW1);
    float* b2s = b1s + 64;
    float* b3s = b2s + 64;

    const int tid  = threadIdx.x;
    const int b    = blockIdx.y;
    const int pblk = blockIdx.x * 128;

    for (int idx = tid; idx < 2048; idx += 512) {
        int o = idx >> 5, p = idx & 31, c = 2*p;
        uint32_t h, l;
        bf16x2_split(W2[o*64 + c], W2[o*64 + c + 1], h, l);
        W2h[o*LDW + p] = h; W2l[o*LDW + p] = l;
        bf16x2_split(W3[o*64 + c], W3[o*64 + c + 1], h, l);
        W3h[o*LDW + p] = h; W3l[o*LDW + p] = l;
    }
    if (tid < 512) {
        int o = tid >> 3, p = tid & 7, c = 2*p;
        uint32_t h, l;
        bf16x2_split(W1[o*16 + c], W1[o*16 + c + 1], h, l);
        W1h[o*LDW1 + p] = h; W1l[o*LDW1 + p] = l;
    }
    if (tid < 64) { b1s[tid] = b1[tid]; b2s[tid] = b2[tid]; b3s[tid] = b3[tid]; }

    const float* xb = x + b*64*HW_ + pblk;
    const float* eb = e + b*16*HW_ + pblk;
    for (int idx = tid; idx < 32*128; idx += 512) {
        int cp = idx >> 7, p = idx & 127;
        uint32_t h, l;
        bf16x2_split(xb[(2*cp)*HW_ + p], xb[(2*cp+1)*HW_ + p], h, l);
        Xph[p*LDW + cp] = h; Xpl[p*LDW + cp] = l;
    }
    for (int idx = tid; idx < 8*128; idx += 512) {
        int cp = idx >> 7, p = idx & 127;
        uint32_t h, l;
        bf16x2_split(eb[(2*cp)*HW_ + p], eb[(2*cp+1)*HW_ + p], h, l);
        Eph[p*LDW1 + cp] = h; Epl[p*LDW1 + cp] = l;
    }
    __syncthreads();

    const int warp = tid >> 5;
    const int lane = tid & 31;
    const int g4 = lane >> 2;
    const int tg = lane & 3;
    const int wb = warp & 7;
    const int wh = warp >> 3;
    const int p0 = wb*16;
    const int o0 = wh*32;

    const int arow = ((lane >> 3) & 1)*8 + (lane & 7);
    const int acol = (lane >> 4)*4;
    const uint32_t adrW2_0 = (uint32_t)__cvta_generic_to_shared(
        &W2h[(o0 + arow)*LDW + acol]);
    const uint32_t adrW2_1 = (uint32_t)__cvta_generic_to_shared(
        &W2h[(o0 + 16 + arow)*LDW + acol]);
    const uint32_t adrW3_0 = (uint32_t)__cvta_generic_to_shared(
        &W3h[(o0 + arow)*LDW + acol]);
    const uint32_t adrW3_1 = (uint32_t)__cvta_generic_to_shared(
        &W3h[(o0 + 16 + arow)*LDW + acol]);
    const uint32_t adrW1_0 = (uint32_t)__cvta_generic_to_shared(
        &W1h[(o0 + arow)*LDW1 + acol]);
    const uint32_t adrW1_1 = (uint32_t)__cvta_generic_to_shared(
        &W1h[(o0 + 16 + arow)*LDW1 + acol]);
    const int btile = lane >> 3;
    const int brow  = p0 + (btile >> 1)*8 + (lane & 7);
    const int bcol  = (btile & 1)*4;
    const uint32_t adrX = (uint32_t)__cvta_generic_to_shared(
        &Xph[brow*LDW + bcol]);
    const uint32_t adrE = (uint32_t)__cvta_generic_to_shared(
        &Eph[brow*LDW1 + bcol]);

    float accV[2][2][4], accK[2][2][4], accQ[2][2][4];
    #pragma unroll
    for (int mt = 0; mt < 2; mt++) {
        int r = o0 + mt*16 + g4;
        float v0 = b2s[r], v1 = b2s[r+8];
        float k0 = b3s[r], k1 = b3s[r+8];
        float q0 = b1s[r], q1 = b1s[r+8];
        #pragma unroll
        for (int ntl = 0; ntl < 2; ntl++) {
            accV[mt][ntl][0] = v0; accV[mt][ntl][1] = v0;
            accV[mt][ntl][2] = v1; accV[mt][ntl][3] = v1;
            accK[mt][ntl][0] = k0; accK[mt][ntl][1] = k0;
            accK[mt][ntl][2] = k1; accK[mt][ntl][3] = k1;
            accQ[mt][ntl][0] = q0; accQ[mt][ntl][1] = q0;
            accQ[mt][ntl][2] = q1; accQ[mt][ntl][3] = q1;
        }
    }

    #pragma unroll
    for (int ks = 0; ks < 4; ks++) {
        const uint32_t ko = ks*32;
        uint32_t bxh[4], bxl[4];
        ldsm_x4(bxh, adrX + ko);
        ldsm_x4(bxl, adrX + ko + XHL);
        #pragma unroll
        for (int mt = 0; mt < 2; mt++) {
            const uint32_t aw2 = (mt ? adrW2_1 : adrW2_0) + ko;
            const uint32_t aw3 = (mt ? adrW3_1 : adrW3_0) + ko;
            uint32_t a2h[4], a2l[4], a3h[4], a3l[4];
            ldsm_x4(a2h, aw2);
            ldsm_x4(a2l, aw2 + WHL);
            ldsm_x4(a3h, aw3);
            ldsm_x4(a3l, aw3 + WHL);
            mma_bf16(accV[mt][0], a2h, bxh[0], bxh[1]);
            mma_bf16(accV[mt][0], a2l, bxh[0], bxh[1]);
            mma_bf16(accV[mt][0], a2h, bxl[0], bxl[1]);
            mma_bf16(accV[mt][1], a2h, bxh[2], bxh[3]);
            mma_bf16(accV[mt][1], a2l, bxh[2], bxh[3]);
            mma_bf16(accV[mt][1], a2h, bxl[2], bxl[3]);
            mma_bf16(accK[mt][0], a3h, bxh[0], bxh[1]);
            mma_bf16(accK[mt][0], a3l, bxh[0], bxh[1]);
            mma_bf16(accK[mt][0], a3h, bxl[0], bxl[1]);
            mma_bf16(accK[mt][1], a3h, bxh[2], bxh[3]);
            mma_bf16(accK[mt][1], a3l, bxh[2], bxh[3]);
            mma_bf16(accK[mt][1], a3h, bxl[2], bxl[3]);
        }
    }

    {
        uint32_t beh[4], bel[4];
        ldsm_x4(beh, adrE);
        ldsm_x4(bel, adrE + EHL);
        #pragma unroll
        for (int mt = 0; mt < 2; mt++) {
            const uint32_t aw1 = mt ? adrW1_1 : adrW1_0;
            uint32_t a1h[4], a1l[4];
            ldsm_x4(a1h, aw1);
            ldsm_x4(a1l, aw1 + W1HL);
            mma_bf16(accQ[mt][0], a1h, beh[0], beh[1]);
            mma_bf16(accQ[mt][0], a1l, beh[0], beh[1]);
            mma_bf16(accQ[mt][0], a1h, bel[0], bel[1]);
            mma_bf16(accQ[mt][1], a1h, beh[2], beh[3]);
            mma_bf16(accQ[mt][1], a1l, beh[2], beh[3]);
            mma_bf16(accQ[mt][1], a1h, bel[2], bel[3]);
        }
    }

    #pragma unroll
    for (int mt = 0; mt < 2; mt++) {
        int r = o0 + mt*16 + g4;
        #pragma unroll
        for (int ntl = 0; ntl < 2; ntl++) {
            int pc = pblk + p0 + ntl*8 + 2*tg;
            int pq = pc >> 1;
            int n0 = b*64 + r, n1 = n0 + 8;
            uint32_t h, l;
            bf16x2_split(accQ[mt][ntl][0], accQ[mt][ntl][1], h, l);
            g_Qh[n0*HWP + pq] = h; g_Ql[n0*HWP + pq] = l;
            bf16x2_split(accQ[mt][ntl][2], accQ[mt][ntl][3], h, l);
            g_Qh[n1*HWP + pq] = h; g_Ql[n1*HWP + pq] = l;
            bf16x2_split(accV[mt][ntl][0], accV[mt][ntl][1], h, l);
            g_Vh[n0*HWP + pq] = h; g_Vl[n0*HWP + pq] = l;
            bf16x2_split(accV[mt][ntl][2], accV[mt][ntl][3], h, l);
            g_Vh[n1*HWP + pq] = h; g_Vl[n1*HWP + pq] = l;
            *(float2*)&g_K[n0*HW_ + pc] = make_float2(accK[mt][ntl][0], accK[mt][ntl][1]);
            *(float2*)&g_K[n1*HW_ + pc] = make_float2(accK[mt][ntl][2], accK[mt][ntl][3]);
        }
    }
}

// ---------------------------------------------------------------------------
// Kernel 2: per-head attention. Phase A and C both fully LDSM-fed.
// A-buf: Qp -> Pp ([128][LDP] k-pairs). B-buf: Vp [128][LDP] -> Ktp [128][LDP]
// (Ktp[w][gp] = pack(K[2gp][w], K[2gp+1][w]) — same shape as Vp, so phase C
// reuses phase A's ldmatrix addresses verbatim).
// ---------------------------------------------------------------------------
#define LDP 68
#define HL_OFF (128*LDP*4)

__global__ __launch_bounds__(1024) void attn_kernel(float* __restrict__ out)
{
    extern __shared__ uint32_t smu[];
    uint32_t* Ah = smu;
    uint32_t* Al = Ah + 128*LDP;
    uint32_t* Bh = Al + 128*LDP;
    uint32_t* Bl = Bh + 128*LDP;
    float* redM = (float*)(Bl + 128*LDP);
    float* redS = redM + 512;

    const int tid  = threadIdx.x;
    const int warp = tid >> 5;
    const int lane = tid & 31;
    const int wb   = warp & 7;
    const int wq   = warp >> 3;
    const int n    = blockIdx.x;
    const uint32_t* Qh = g_Qh + n*HWP;
    const uint32_t* Ql = g_Ql + n*HWP;
    const uint32_t* Vh = g_Vh + n*HWP;
    const uint32_t* Vl = g_Vl + n*HWP;
    const float*    K  = g_K  + n*HW_;

    for (int idx = tid; idx < HWP; idx += 1024) {
        int r = idx >> 6, c = idx & 63;
        Ah[r*LDP + c] = Qh[idx];
        Al[r*LDP + c] = Ql[idx];
        Bh[r*LDP + c] = Vh[idx];
        Bl[r*LDP + c] = Vl[idx];
    }
    __syncthreads();

    const int g4 = lane >> 2;
    const int tg = lane & 3;
    const int r0 = wb*16 + g4;
    const int nt0 = wq*4;

    const int rowA = wb*16 + ((lane >> 3) & 1)*8 + (lane & 7);
    const int colA = (lane >> 4)*4;
    const uint32_t adrA =
        (uint32_t)__cvta_generic_to_shared(&Ah[rowA*LDP + colA]);
    const int tile  = lane >> 3;
    const int rowB0 = (nt0 + (tile >> 1))*8 + (lane & 7);
    const int rowB1 = (nt0 + 2 + (tile >> 1))*8 + (lane & 7);
    const int colB  = (tile & 1)*4;
    const uint32_t adrB0 =
        (uint32_t)__cvta_generic_to_shared(&Bh[rowB0*LDP + colB]);
    const uint32_t adrB1 =
        (uint32_t)__cvta_generic_to_shared(&Bh[rowB1*LDP + colB]);

    float acc[4][4];
    #pragma unroll
    for (int j = 0; j < 4; j++)
        #pragma unroll
        for (int i = 0; i < 4; i++) acc[j][i] = 0.0f;

    // ---- Phase A: S = Q @ V^T
    #pragma unroll 2
    for (int k = 0; k < 8; k++) {
        const uint32_t koff = k*32;
        uint32_t ah[4], al[4], b0h[4], b0l[4], b1h[4], b1l[4];
        ldsm_x4(ah, adrA + koff);
        ldsm_x4(al, adrA + koff + HL_OFF);
        ldsm_x4(b0h, adrB0 + koff);
        ldsm_x4(b0l, adrB0 + koff + HL_OFF);
        ldsm_x4(b1h, adrB1 + koff);
        ldsm_x4(b1l, adrB1 + koff + HL_OFF);
        mma_bf16(acc[0], ah, b0h[0], b0h[1]);
        mma_bf16(acc[0], al, b0h[0], b0h[1]);
        mma_bf16(acc[0], ah, b0l[0], b0l[1]);
        mma_bf16(acc[1], ah, b0h[2], b0h[3]);
        mma_bf16(acc[1], al, b0h[2], b0h[3]);
        mma_bf16(acc[1], ah, b0l[2], b0l[3]);
        mma_bf16(acc[2], ah, b1h[0], b1h[1]);
        mma_bf16(acc[2], al, b1h[0], b1h[1]);
        mma_bf16(acc[2], ah, b1l[0], b1l[1]);
        mma_bf16(acc[3], ah, b1h[2], b1h[3]);
        mma_bf16(acc[3], al, b1h[2], b1h[3]);
        mma_bf16(acc[3], ah, b1l[2], b1l[3]);
    }

    // ---- Softmax (4-warp row groups)
    float m1 = -1e30f, m2 = -1e30f;
    #pragma unroll
    for (int j = 0; j < 4; j++) {
        m1 = fmaxf(m1, fmaxf(acc[j][0], acc[j][1]));
        m2 = fmaxf(m2, fmaxf(acc[j][2], acc[j][3]));
    }
    #pragma unroll
    for (int off = 1; off < 4; off <<= 1) {
        m1 = fmaxf(m1, __shfl_xor_sync(0xFFFFFFFFu, m1, off));
        m2 = fmaxf(m2, __shfl_xor_sync(0xFFFFFFFFu, m2, off));
    }
    if (tg == 0) {
        redM[wq*128 + r0]     = m1;
        redM[wq*128 + r0 + 8] = m2;
    }
    __syncthreads();

    const float gm1 = fmaxf(fmaxf(redM[r0],       redM[128 + r0]),
                            fmaxf(redM[256 + r0], redM[384 + r0]));
    const float gm2 = fmaxf(fmaxf(redM[r0+8],       redM[128 + r0+8]),
                            fmaxf(redM[256 + r0+8], redM[384 + r0+8]));

    float s1 = 0.0f, s2 = 0.0f;
    #pragma unroll
    for (int j = 0; j < 4; j++) {
        acc[j][0] = __expf(acc[j][0] - gm1);
        acc[j][1] = __expf(acc[j][1] - gm1);
        acc[j][2] = __expf(acc[j][2] - gm2);
        acc[j][3] = __expf(acc[j][3] - gm2);
        s1 += acc[j][0] + acc[j][1];
        s2 += acc[j][2] + acc[j][3];
    }
    #pragma unroll
    for (int off = 1; off < 4; off <<= 1) {
        s1 += __shfl_xor_sync(0xFFFFFFFFu, s1, off);
        s2 += __shfl_xor_sync(0xFFFFFFFFu, s2, off);
    }
    if (tg == 0) {
        redS[wq*128 + r0]     = s1;
        redS[wq*128 + r0 + 8] = s2;
    }

    // Store P split into A-buf (each thread's acc pair = one k-pair)
    #pragma unroll
    for (int j = 0; j < 4; j++) {
        const int pb = (nt0 + j)*4 + tg;
        uint32_t h, l;
        bf16x2_split(acc[j][0], acc[j][1], h, l);
        Ah[r0*LDP + pb] = h; Al[r0*LDP + pb] = l;
        bf16x2_split(acc[j][2], acc[j][3], h, l);
        Ah[(r0+8)*LDP + pb] = h; Al[(r0+8)*LDP + pb] = l;
    }
    // Stage K transposed + g-pair packed: Ktp[w][gp] = pack(K[2gp][w], K[2gp+1][w])
    for (int idx = tid; idx < 64*128; idx += 1024) {
        int gp = idx >> 7, w = idx & 127;
        uint32_t h, l;
        bf16x2_split(K[(2*gp)*128 + w], K[(2*gp+1)*128 + w], h, l);
        Bh[w*LDP + gp] = h; Bl[w*LDP + gp] = l;
    }
    __syncthreads();

    const float inv1 = 1.0f / (redS[r0] + redS[128 + r0] +
                               redS[256 + r0] + redS[384 + r0]);
    const float inv2 = 1.0f / (redS[r0+8] + redS[128 + r0+8] +
                               redS[256 + r0+8] + redS[384 + r0+8]);

    // ---- Phase C: ctx = P @ K — identical structure to phase A
    float oac[4][4];
    #pragma unroll
    for (int j = 0; j < 4; j++)
        #pragma unroll
        for (int i = 0; i < 4; i++) oac[j][i] = 0.0f;

    #pragma unroll 2
    for (int k = 0; k < 8; k++) {
        const uint32_t koff = k*32;
        uint32_t ah[4], al[4], b0h[4], b0l[4], b1h[4], b1l[4];
        ldsm_x4(ah, adrA + koff);
        ldsm_x4(al, adrA + koff + HL_OFF);
        ldsm_x4(b0h, adrB0 + koff);
        ldsm_x4(b0l, adrB0 + koff + HL_OFF);
        ldsm_x4(b1h, adrB1 + koff);
        ldsm_x4(b1l, adrB1 + koff + HL_OFF);
        mma_bf16(oac[0], ah, b0h[0], b0h[1]);
        mma_bf16(oac[0], al, b0h[0], b0h[1]);
        mma_bf16(oac[0], ah, b0l[0], b0l[1]);
        mma_bf16(oac[1], ah, b0h[2], b0h[3]);
        mma_bf16(oac[1], al, b0h[2], b0h[3]);
        mma_bf16(oac[1], ah, b0l[2], b0l[3]);
        mma_bf16(oac[2], ah, b1h[0], b1h[1]);
        mma_bf16(oac[2], al, b1h[0], b1h[1]);
        mma_bf16(oac[2], ah, b1l[0], b1l[1]);
        mma_bf16(oac[3], ah, b1h[2], b1h[3]);
        mma_bf16(oac[3], al, b1h[2], b1h[3]);
        mma_bf16(oac[3], ah, b1l[2], b1l[3]);
    }

    // Epilogue
    #pragma unroll
    for (int j = 0; j < 4; j++) {
        const int cb = (nt0 + j)*8 + 2*tg;
        *(float2*)&out[n*HW_ + r0*128 + cb] =
            make_float2(oac[j][0]*inv1, oac[j][1]*inv1);
        *(float2*)&out[n*HW_ + (r0+8)*128 + cb] =
            make_float2(oac[j][2]*inv2, oac[j][3]*inv2);
    }
}

// ---------------------------------------------------------------------------
extern "C" void kernel_launch(void* const* d_in, const int* in_sizes, int n_in,
                              void* d_out, int out_size)
{
    const float* x  = (const float*)d_in[0];
    const float* e  = (const float*)d_in[1];
    const float* W1 = (const float*)d_in[2];
    const float* b1 = (const float*)d_in[3];
    const float* W2 = (const float*)d_in[4];
    const float* b2 = (const float*)d_in[5];
    const float* W3 = (const float*)d_in[6];
    const float* b3 = (const float*)d_in[7];
    float* out = (float*)d_out;

    const int smem1 = (4*64*LDW + 2*64*LDW1 + 2*128*LDW + 2*128*LDW1) * 4
                      + 3*64*4;
    cudaFuncSetAttribute(qvk_kernel, cudaFuncAttributeMaxDynamicSharedMemorySize, smem1);
    qvk_kernel<<<dim3(128, 16), 512, smem1>>>(x, e, W1, b1, W2, b2, W3, b3);

    const int smem2 = (4*128*LDP) * 4 + 2*512*4;
    cudaFuncSetAttribute(attn_kernel, cudaFuncAttributeMaxDynamicSharedMemorySize, smem2);
    attn_kernel<<<NTOT, 1024, smem2>>>(out);
}

// round 15
// speedup vs baseline: 1.7888x; 1.0476x over previous
#include <cuda_runtime.h>
#include <cstdint>

#define HW_ (128*128)
#define NTOT (16*64)
#define HWP (HW_/2)

__device__ uint32_t g_Qh[NTOT * HWP];
__device__ uint32_t g_Ql[NTOT * HWP];
__device__ uint32_t g_Vh[NTOT * HWP];
__device__ uint32_t g_Vl[NTOT * HWP];
__device__ float    g_K [NTOT * HW_];

// ---- bf16x3 helpers ---------------------------------------------------------
__device__ __forceinline__ void mma_bf16(float c[4], const uint32_t a[4],
                                         const uint32_t b0, const uint32_t b1) {
    asm volatile(
        "mma.sync.aligned.m16n8k16.row.col.f32.bf16.bf16.f32 "
        "{%0,%1,%2,%3}, {%4,%5,%6,%7}, {%8,%9}, {%0,%1,%2,%3};"
        : "+f"(c[0]), "+f"(c[1]), "+f"(c[2]), "+f"(c[3])
        : "r"(a[0]), "r"(a[1]), "r"(a[2]), "r"(a[3]), "r"(b0), "r"(b1));
}

__device__ __forceinline__ void bf16x2_split(float x, float y,
                                             uint32_t& hi2, uint32_t& lo2) {
    uint32_t h;
    asm("cvt.rn.bf16x2.f32 %0, %1, %2;" : "=r"(h) : "f"(y), "f"(x));
    float xh = __uint_as_float(h << 16);
    float yh = __uint_as_float(h & 0xffff0000u);
    float xl = x - xh;
    float yl = y - yh;
    hi2 = h;
    asm("cvt.rn.bf16x2.f32 %0, %1, %2;" : "=r"(lo2) : "f"(yl), "f"(xl));
}

__device__ __forceinline__ void ldsm_x4(uint32_t r[4], uint32_t addr) {
    asm volatile(
        "ldmatrix.sync.aligned.m8n8.x4.shared.b16 {%0,%1,%2,%3}, [%4];"
        : "=r"(r[0]), "=r"(r[1]), "=r"(r[2]), "=r"(r[3]) : "r"(addr));
}

// ---------------------------------------------------------------------------
// Kernel 1: fused 1x1-conv projections. 256 CTAs, 8 pixel tiles per CTA:
// weight pre-split amortized 8x. Mainloop identical to R13/R14.
// ---------------------------------------------------------------------------
#define LDW  36
#define LDW1 12
#define WHL  (64*LDW*4)
#define W1HL (64*LDW1*4)
#define XHL  (128*LDW*4)
#define EHL  (128*LDW1*4)
#define NTILE 8

__global__ __launch_bounds__(512) void qvk_kernel(
    const float* __restrict__ x, const float* __restrict__ e,
    const float* __restrict__ W1, const float* __restrict__ b1,
    const float* __restrict__ W2, const float* __restrict__ b2,
    const float* __restrict__ W3, const float* __restrict__ b3)
{
    extern __shared__ uint32_t smu[];
    uint32_t* W2h = smu;
    uint32_t* W2l = W2h + 64*LDW;
    uint32_t* W3h = W2l + 64*LDW;
    uint32_t* W3l = W3h + 64*LDW;
    uint32_t* W1h = W3l + 64*LDW;
    uint32_t* W1l = W1h + 64*LDW1;
    uint32_t* Xph = W1l + 64*LDW1;
    uint32_t* Xpl = Xph + 128*LDW;
    uint32_t* Eph = Xpl + 128*LDW;
    uint32_t* Epl = Eph + 128*LDW1;
    float* b1s = (float*)(Epl + 128*LDW1);
    float* b2s = b1s + 64;
    float* b3s = b2s + 64;

    const int tid = threadIdx.x;
    const int b   = blockIdx.y;

    // ---- One-time prologue: weights + biases
    for (int idx = tid; idx < 2048; idx += 512) {
        int o = idx >> 5, p = idx & 31, c = 2*p;
        uint32_t h, l;
        bf16x2_split(W2[o*64 + c], W2[o*64 + c + 1], h, l);
        W2h[o*LDW + p] = h; W2l[o*LDW + p] = l;
        bf16x2_split(W3[o*64 + c], W3[o*64 + c + 1], h, l);
        W3h[o*LDW + p] = h; W3l[o*LDW + p] = l;
    }
    if (tid < 512) {
        int o = tid >> 3, p = tid & 7, c = 2*p;
        uint32_t h, l;
        bf16x2_split(W1[o*16 + c], W1[o*16 + c + 1], h, l);
        W1h[o*LDW1 + p] = h; W1l[o*LDW1 + p] = l;
    }
    if (tid < 64) { b1s[tid] = b1[tid]; b2s[tid] = b2[tid]; b3s[tid] = b3[tid]; }

    const int warp = tid >> 5;
    const int lane = tid & 31;
    const int g4 = lane >> 2;
    const int tg = lane & 3;
    const int wb = warp & 7;
    const int wh = warp >> 3;
    const int p0 = wb*16;
    const int o0 = wh*32;

    // ldmatrix lane addresses (tile-invariant)
    const int arow = ((lane >> 3) & 1)*8 + (lane & 7);
    const int acol = (lane >> 4)*4;
    const uint32_t adrW2_0 = (uint32_t)__cvta_generic_to_shared(
        &W2h[(o0 + arow)*LDW + acol]);
    const uint32_t adrW2_1 = (uint32_t)__cvta_generic_to_shared(
        &W2h[(o0 + 16 + arow)*LDW + acol]);
    const uint32_t adrW3_0 = (uint32_t)__cvta_generic_to_shared(
        &W3h[(o0 + arow)*LDW + acol]);
    const uint32_t adrW3_1 = (uint32_t)__cvta_generic_to_shared(
        &W3h[(o0 + 16 + arow)*LDW + acol]);
    const uint32_t adrW1_0 = (uint32_t)__cvta_generic_to_shared(
        &W1h[(o0 + arow)*LDW1 + acol]);
    const uint32_t adrW1_1 = (uint32_t)__cvta_generic_to_shared(
        &W1h[(o0 + 16 + arow)*LDW1 + acol]);
    const int btile = lane >> 3;
    const int brow  = p0 + (btile >> 1)*8 + (lane & 7);
    const int bcol  = (btile & 1)*4;
    const uint32_t adrX = (uint32_t)__cvta_generic_to_shared(
        &Xph[brow*LDW + bcol]);
    const uint32_t adrE = (uint32_t)__cvta_generic_to_shared(
        &Eph[brow*LDW1 + bcol]);

    // ---- Loop over 8 pixel tiles
    for (int t = 0; t < NTILE; t++) {
        const int pblk = (blockIdx.x*NTILE + t) * 128;
        const float* xb = x + b*64*HW_ + pblk;
        const float* eb = e + b*16*HW_ + pblk;

        __syncthreads();   // previous mainloop reads done before restaging
        for (int idx = tid; idx < 32*128; idx += 512) {
            int cp = idx >> 7, p = idx & 127;
            uint32_t h, l;
            bf16x2_split(xb[(2*cp)*HW_ + p], xb[(2*cp+1)*HW_ + p], h, l);
            Xph[p*LDW + cp] = h; Xpl[p*LDW + cp] = l;
        }
        for (int idx = tid; idx < 8*128; idx += 512) {
            int cp = idx >> 7, p = idx & 127;
            uint32_t h, l;
            bf16x2_split(eb[(2*cp)*HW_ + p], eb[(2*cp+1)*HW_ + p], h, l);
            Eph[p*LDW1 + cp] = h; Epl[p*LDW1 + cp] = l;
        }
        __syncthreads();

        float accV[2][2][4], accK[2][2][4], accQ[2][2][4];
        #pragma unroll
        for (int mt = 0; mt < 2; mt++) {
            int r = o0 + mt*16 + g4;
            float v0 = b2s[r], v1 = b2s[r+8];
            float k0 = b3s[r], k1 = b3s[r+8];
            float q0 = b1s[r], q1 = b1s[r+8];
            #pragma unroll
            for (int ntl = 0; ntl < 2; ntl++) {
                accV[mt][ntl][0] = v0; accV[mt][ntl][1] = v0;
                accV[mt][ntl][2] = v1; accV[mt][ntl][3] = v1;
                accK[mt][ntl][0] = k0; accK[mt][ntl][1] = k0;
                accK[mt][ntl][2] = k1; accK[mt][ntl][3] = k1;
                accQ[mt][ntl][0] = q0; accQ[mt][ntl][1] = q0;
                accQ[mt][ntl][2] = q1; accQ[mt][ntl][3] = q1;
            }
        }

        #pragma unroll
        for (int ks = 0; ks < 4; ks++) {
            const uint32_t ko = ks*32;
            uint32_t bxh[4], bxl[4];
            ldsm_x4(bxh, adrX + ko);
            ldsm_x4(bxl, adrX + ko + XHL);
            #pragma unroll
            for (int mt = 0; mt < 2; mt++) {
                const uint32_t aw2 = (mt ? adrW2_1 : adrW2_0) + ko;
                const uint32_t aw3 = (mt ? adrW3_1 : adrW3_0) + ko;
                uint32_t a2h[4], a2l[4], a3h[4], a3l[4];
                ldsm_x4(a2h, aw2);
                ldsm_x4(a2l, aw2 + WHL);
                ldsm_x4(a3h, aw3);
                ldsm_x4(a3l, aw3 + WHL);
                mma_bf16(accV[mt][0], a2h, bxh[0], bxh[1]);
                mma_bf16(accV[mt][0], a2l, bxh[0], bxh[1]);
                mma_bf16(accV[mt][0], a2h, bxl[0], bxl[1]);
                mma_bf16(accV[mt][1], a2h, bxh[2], bxh[3]);
                mma_bf16(accV[mt][1], a2l, bxh[2], bxh[3]);
                mma_bf16(accV[mt][1], a2h, bxl[2], bxl[3]);
                mma_bf16(accK[mt][0], a3h, bxh[0], bxh[1]);
                mma_bf16(accK[mt][0], a3l, bxh[0], bxh[1]);
                mma_bf16(accK[mt][0], a3h, bxl[0], bxl[1]);
                mma_bf16(accK[mt][1], a3h, bxh[2], bxh[3]);
                mma_bf16(accK[mt][1], a3l, bxh[2], bxh[3]);
                mma_bf16(accK[mt][1], a3h, bxl[2], bxl[3]);
            }
        }

        {
            uint32_t beh[4], bel[4];
            ldsm_x4(beh, adrE);
            ldsm_x4(bel, adrE + EHL);
            #pragma unroll
            for (int mt = 0; mt < 2; mt++) {
                const uint32_t aw1 = mt ? adrW1_1 : adrW1_0;
                uint32_t a1h[4], a1l[4];
                ldsm_x4(a1h, aw1);
                ldsm_x4(a1l, aw1 + W1HL);
                mma_bf16(accQ[mt][0], a1h, beh[0], beh[1]);
                mma_bf16(accQ[mt][0], a1l, beh[0], beh[1]);
                mma_bf16(accQ[mt][0], a1h, bel[0], bel[1]);
                mma_bf16(accQ[mt][1], a1h, beh[2], beh[3]);
                mma_bf16(accQ[mt][1], a1l, beh[2], beh[3]);
                mma_bf16(accQ[mt][1], a1h, bel[2], bel[3]);
            }
        }

        #pragma unroll
        for (int mt = 0; mt < 2; mt++) {
            int r = o0 + mt*16 + g4;
            #pragma unroll
            for (int ntl = 0; ntl < 2; ntl++) {
                int pc = pblk + p0 + ntl*8 + 2*tg;
                int pq = pc >> 1;
                int n0 = b*64 + r, n1 = n0 + 8;
                uint32_t h, l;
                bf16x2_split(accQ[mt][ntl][0], accQ[mt][ntl][1], h, l);
                g_Qh[n0*HWP + pq] = h; g_Ql[n0*HWP + pq] = l;
                bf16x2_split(accQ[mt][ntl][2], accQ[mt][ntl][3], h, l);
                g_Qh[n1*HWP + pq] = h; g_Ql[n1*HWP + pq] = l;
                bf16x2_split(accV[mt][ntl][0], accV[mt][ntl][1], h, l);
                g_Vh[n0*HWP + pq] = h; g_Vl[n0*HWP + pq] = l;
                bf16x2_split(accV[mt][ntl][2], accV[mt][ntl][3], h, l);
                g_Vh[n1*HWP + pq] = h; g_Vl[n1*HWP + pq] = l;
                *(float2*)&g_K[n0*HW_ + pc] = make_float2(accK[mt][ntl][0], accK[mt][ntl][1]);
                *(float2*)&g_K[n1*HW_ + pc] = make_float2(accK[mt][ntl][2], accK[mt][ntl][3]);
            }
        }
    }
}

// ---------------------------------------------------------------------------
// Kernel 2: per-head attention (R14 winner, unchanged).
// ---------------------------------------------------------------------------
#define LDP 68
#define HL_OFF (128*LDP*4)

__global__ __launch_bounds__(1024) void attn_kernel(float* __restrict__ out)
{
    extern __shared__ uint32_t smu[];
    uint32_t* Ah = smu;
    uint32_t* Al = Ah + 128*LDP;
    uint32_t* Bh = Al + 128*LDP;
    uint32_t* Bl = Bh + 128*LDP;
    float* redM = (float*)(Bl + 128*LDP);
    float* redS = redM + 512;

    const int tid  = threadIdx.x;
    const int warp = tid >> 5;
    const int lane = tid & 31;
    const int wb   = warp & 7;
    const int wq   = warp >> 3;
    const int n    = blockIdx.x;
    const uint32_t* Qh = g_Qh + n*HWP;
    const uint32_t* Ql = g_Ql + n*HWP;
    const uint32_t* Vh = g_Vh + n*HWP;
    const uint32_t* Vl = g_Vl + n*HWP;
    const float*    K  = g_K  + n*HW_;

    for (int idx = tid; idx < HWP; idx += 1024) {
        int r = idx >> 6, c = idx & 63;
        Ah[r*LDP + c] = Qh[idx];
        Al[r*LDP + c] = Ql[idx];
        Bh[r*LDP + c] = Vh[idx];
        Bl[r*LDP + c] = Vl[idx];
    }
    __syncthreads();

    const int g4 = lane >> 2;
    const int tg = lane & 3;
    const int r0 = wb*16 + g4;
    const int nt0 = wq*4;

    const int rowA = wb*16 + ((lane >> 3) & 1)*8 + (lane & 7);
    const int colA = (lane >> 4)*4;
    const uint32_t adrA =
        (uint32_t)__cvta_generic_to_shared(&Ah[rowA*LDP + colA]);
    const int tile  = lane >> 3;
    const int rowB0 = (nt0 + (tile >> 1))*8 + (lane & 7);
    const int rowB1 = (nt0 + 2 + (tile >> 1))*8 + (lane & 7);
    const int colB  = (tile & 1)*4;
    const uint32_t adrB0 =
        (uint32_t)__cvta_generic_to_shared(&Bh[rowB0*LDP + colB]);
    const uint32_t adrB1 =
        (uint32_t)__cvta_generic_to_shared(&Bh[rowB1*LDP + colB]);

    float acc[4][4];
    #pragma unroll
    for (int j = 0; j < 4; j++)
        #pragma unroll
        for (int i = 0; i < 4; i++) acc[j][i] = 0.0f;

    #pragma unroll 2
    for (int k = 0; k < 8; k++) {
        const uint32_t koff = k*32;
        uint32_t ah[4], al[4], b0h[4], b0l[4], b1h[4], b1l[4];
        ldsm_x4(ah, adrA + koff);
        ldsm_x4(al, adrA + koff + HL_OFF);
        ldsm_x4(b0h, adrB0 + koff);
        ldsm_x4(b0l, adrB0 + koff + HL_OFF);
        ldsm_x4(b1h, adrB1 + koff);
        ldsm_x4(b1l, adrB1 + koff + HL_OFF);
        mma_bf16(acc[0], ah, b0h[0], b0h[1]);
        mma_bf16(acc[0], al, b0h[0], b0h[1]);
        mma_bf16(acc[0], ah, b0l[0], b0l[1]);
        mma_bf16(acc[1], ah, b0h[2], b0h[3]);
        mma_bf16(acc[1], al, b0h[2], b0h[3]);
        mma_bf16(acc[1], ah, b0l[2], b0l[3]);
        mma_bf16(acc[2], ah, b1h[0], b1h[1]);
        mma_bf16(acc[2], al, b1h[0], b1h[1]);
        mma_bf16(acc[2], ah, b1l[0], b1l[1]);
        mma_bf16(acc[3], ah, b1h[2], b1h[3]);
        mma_bf16(acc[3], al, b1h[2], b1h[3]);
        mma_bf16(acc[3], ah, b1l[2], b1l[3]);
    }

    float m1 = -1e30f, m2 = -1e30f;
    #pragma unroll
    for (int j = 0; j < 4; j++) {
        m1 = fmaxf(m1, fmaxf(acc[j][0], acc[j][1]));
        m2 = fmaxf(m2, fmaxf(acc[j][2], acc[j][3]));
    }
    #pragma unroll
    for (int off = 1; off < 4; off <<= 1) {
        m1 = fmaxf(m1, __shfl_xor_sync(0xFFFFFFFFu, m1, off));
        m2 = fmaxf(m2, __shfl_xor_sync(0xFFFFFFFFu, m2, off));
    }
    if (tg == 0) {
        redM[wq*128 + r0]     = m1;
        redM[wq*128 + r0 + 8] = m2;
    }
    __syncthreads();

    const float gm1 = fmaxf(fmaxf(redM[r0],       redM[128 + r0]),
                            fmaxf(redM[256 + r0], redM[384 + r0]));
    const float gm2 = fmaxf(fmaxf(redM[r0+8],       redM[128 + r0+8]),
                            fmaxf(redM[256 + r0+8], redM[384 + r0+8]));

    float s1 = 0.0f, s2 = 0.0f;
    #pragma unroll
    for (int j = 0; j < 4; j++) {
        acc[j][0] = __expf(acc[j][0] - gm1);
        acc[j][1] = __expf(acc[j][1] - gm1);
        acc[j][2] = __expf(acc[j][2] - gm2);
        acc[j][3] = __expf(acc[j][3] - gm2);
        s1 += acc[j][0] + acc[j][1];
        s2 += acc[j][2] + acc[j][3];
    }
    #pragma unroll
    for (int off = 1; off < 4; off <<= 1) {
        s1 += __shfl_xor_sync(0xFFFFFFFFu, s1, off);
        s2 += __shfl_xor_sync(0xFFFFFFFFu, s2, off);
    }
    if (tg == 0) {
        redS[wq*128 + r0]     = s1;
        redS[wq*128 + r0 + 8] = s2;
    }

    #pragma unroll
    for (int j = 0; j < 4; j++) {
        const int pb = (nt0 + j)*4 + tg;
        uint32_t h, l;
        bf16x2_split(acc[j][0], acc[j][1], h, l);
        Ah[r0*LDP + pb] = h; Al[r0*LDP + pb] = l;
        bf16x2_split(acc[j][2], acc[j][3], h, l);
        Ah[(r0+8)*LDP + pb] = h; Al[(r0+8)*LDP + pb] = l;
    }
    for (int idx = tid; idx < 64*128; idx += 1024) {
        int gp = idx >> 7, w = idx & 127;
        uint32_t h, l;
        bf16x2_split(K[(2*gp)*128 + w], K[(2*gp+1)*128 + w], h, l);
        Bh[w*LDP + gp] = h; Bl[w*LDP + gp] = l;
    }
    __syncthreads();

    const float inv1 = 1.0f / (redS[r0] + redS[128 + r0] +
                               redS[256 + r0] + redS[384 + r0]);
    const float inv2 = 1.0f / (redS[r0+8] + redS[128 + r0+8] +
                               redS[256 + r0+8] + redS[384 + r0+8]);

    float oac[4][4];
    #pragma unroll
    for (int j = 0; j < 4; j++)
        #pragma unroll
        for (int i = 0; i < 4; i++) oac[j][i] = 0.0f;

    #pragma unroll 2
    for (int k = 0; k < 8; k++) {
        const uint32_t koff = k*32;
        uint32_t ah[4], al[4], b0h[4], b0l[4], b1h[4], b1l[4];
        ldsm_x4(ah, adrA + koff);
        ldsm_x4(al, adrA + koff + HL_OFF);
        ldsm_x4(b0h, adrB0 + koff);
        ldsm_x4(b0l, adrB0 + koff + HL_OFF);
        ldsm_x4(b1h, adrB1 + koff);
        ldsm_x4(b1l, adrB1 + koff + HL_OFF);
        mma_bf16(oac[0], ah, b0h[0], b0h[1]);
        mma_bf16(oac[0], al, b0h[0], b0h[1]);
        mma_bf16(oac[0], ah, b0l[0], b0l[1]);
        mma_bf16(oac[1], ah, b0h[2], b0h[3]);
        mma_bf16(oac[1], al, b0h[2], b0h[3]);
        mma_bf16(oac[1], ah, b0l[2], b0l[3]);
        mma_bf16(oac[2], ah, b1h[0], b1h[1]);
        mma_bf16(oac[2], al, b1h[0], b1h[1]);
        mma_bf16(oac[2], ah, b1l[0], b1l[1]);
        mma_bf16(oac[3], ah, b1h[2], b1h[3]);
        mma_bf16(oac[3], al, b1h[2], b1h[3]);
        mma_bf16(oac[3], ah, b1l[2], b1l[3]);
    }

    #pragma unroll
    for (int j = 0; j < 4; j++) {
        const int cb = (nt0 + j)*8 + 2*tg;
        *(float2*)&out[n*HW_ + r0*128 + cb] =
            make_float2(oac[j][0]*inv1, oac[j][1]*inv1);
        *(float2*)&out[n*HW_ + (r0+8)*128 + cb] =
            make_float2(oac[j][2]*inv2, oac[j][3]*inv2);
    }
}

// ---------------------------------------------------------------------------
extern "C" void kernel_launch(void* const* d_in, const int* in_sizes, int n_in,
                              void* d_out, int out_size)
{
    const float* x  = (const float*)d_in[0];
    const float* e  = (const float*)d_in[1];
    const float* W1 = (const float*)d_in[2];
    const float* b1 = (const float*)d_in[3];
    const float* W2 = (const float*)d_in[4];
    const float* b2 = (const float*)d_in[5];
    const float* W3 = (const float*)d_in[6];
    const float* b3 = (const float*)d_in[7];
    float* out = (float*)d_out;

    const int smem1 = (4*64*LDW + 2*64*LDW1 + 2*128*LDW + 2*128*LDW1) * 4
                      + 3*64*4;
    cudaFuncSetAttribute(qvk_kernel, cudaFuncAttributeMaxDynamicSharedMemorySize, smem1);
    qvk_kernel<<<dim3(16, 16), 512, smem1>>>(x, e, W1, b1, W2, b2, W3, b3);

    const int smem2 = (4*128*LDP) * 4 + 2*512*4;
    cudaFuncSetAttribute(attn_kernel, cudaFuncAttributeMaxDynamicSharedMemorySize, smem2);
    attn_kernel<<<NTOT, 1024, smem2>>>(out);
}